// round 2
// baseline (speedup 1.0000x reference)
#include <cuda_runtime.h>
#include <math.h>

#define N_NODES 50000
#define N_EDGES 1600000
#define E_TOT   (N_EDGES + N_NODES)
#define IN_DIM  256
#define HID     128
#define HEADS   4
#define OUT_DIM 2
#define NEG_SLOPE 0.2f

// ---------------- device scratch (static: no runtime allocation) ------------
__device__ float g_xp1[N_NODES * HID];     // layer-1 projected features
__device__ float g_as1[N_NODES * HEADS];   // per-node src attn logits (L1)
__device__ float g_ad1[N_NODES * HEADS];   // per-node dst attn logits (L1)
__device__ float g_xp2[N_NODES * OUT_DIM]; // layer-2 projected features
__device__ float g_as2[N_NODES];
__device__ float g_ad2[N_NODES];
__device__ int   g_cnt[N_NODES];
__device__ int   g_rowstart[N_NODES + 1];
__device__ int   g_cursor[N_NODES];
__device__ int   g_srcs[E_TOT];            // CSR (by dst) source list
__device__ int   g_is64;                   // edge_index dtype flag

// ---------------- dtype probe ------------------------------------------------
// Reference requests int64 but JAX w/o x64 silently yields int32. Values are
// node ids < 50000, so under int64 the odd int32 words are all zero; under
// int32 they are random node ids. Reads only first 512 bytes (safe either way).
__global__ void detect_k(const int* __restrict__ ei32) {
    int all0 = 1;
    #pragma unroll 8
    for (int i = 0; i < 64; i++)
        if (ei32[2 * i + 1] != 0) { all0 = 0; }
    g_is64 = all0;
}

// ---------------- CSR build --------------------------------------------------
__global__ void zero_cnt_k() {
    int i = blockIdx.x * blockDim.x + threadIdx.x;
    if (i < N_NODES) g_cnt[i] = 0;
}

__global__ void count_k(const void* __restrict__ eiv) {
    int i = blockIdx.x * blockDim.x + threadIdx.x;
    if (i >= E_TOT) return;
    int dst;
    if (i < N_EDGES) {
        if (g_is64) dst = (int)((const long long*)eiv)[N_EDGES + i];
        else        dst = ((const int*)eiv)[N_EDGES + i];
    } else {
        dst = i - N_EDGES;
    }
    atomicAdd(&g_cnt[dst], 1);
}

__global__ void scan_k() {
    const int CH = 49;  // 1024 * 49 = 50176 >= N_NODES
    int t = threadIdx.x;
    int base = t * CH;
    int tot = 0;
    for (int j = 0; j < CH; j++) {
        int idx = base + j;
        if (idx < N_NODES) tot += g_cnt[idx];
    }
    __shared__ int wsum[32];
    int lane = t & 31, wid = t >> 5;
    int xincl = tot;
    #pragma unroll
    for (int o = 1; o < 32; o <<= 1) {
        int y = __shfl_up_sync(0xffffffffu, xincl, o);
        if (lane >= o) xincl += y;
    }
    if (lane == 31) wsum[wid] = xincl;
    __syncthreads();
    if (wid == 0) {
        int v = wsum[lane];
        #pragma unroll
        for (int o = 1; o < 32; o <<= 1) {
            int y = __shfl_up_sync(0xffffffffu, v, o);
            if (lane >= o) v += y;
        }
        wsum[lane] = v;
    }
    __syncthreads();
    int off = xincl - tot + (wid > 0 ? wsum[wid - 1] : 0);
    int run = off;
    for (int j = 0; j < CH; j++) {
        int idx = base + j;
        if (idx < N_NODES) {
            g_rowstart[idx] = run;
            g_cursor[idx]   = run;
            run += g_cnt[idx];
        }
    }
    if (t == 1023) g_rowstart[N_NODES] = run;
}

__global__ void scatter_k(const void* __restrict__ eiv) {
    int i = blockIdx.x * blockDim.x + threadIdx.x;
    if (i >= E_TOT) return;
    int src, dst;
    if (i < N_EDGES) {
        if (g_is64) {
            const long long* e = (const long long*)eiv;
            src = (int)e[i]; dst = (int)e[N_EDGES + i];
        } else {
            const int* e = (const int*)eiv;
            src = e[i]; dst = e[N_EDGES + i];
        }
    } else {
        src = dst = i - N_EDGES;
    }
    int p = atomicAdd(&g_cursor[dst], 1);
    g_srcs[p] = src;
}

// ---------------- layer-1 GEMM + attention logits ---------------------------
// 32 rows/block, 256 threads, 4x4 register blocking, K staged in 64-chunks.
__global__ __launch_bounds__(256) void gemm_k(
    const float* __restrict__ x, const float* __restrict__ fi,
    const float* __restrict__ W1,
    const float* __restrict__ attS, const float* __restrict__ attD)
{
    __shared__ float sigf[IN_DIM];
    __shared__ float xs[32 * 64];
    __shared__ float ws[64 * 128];
    int tid = threadIdx.x;
    int tx = tid & 31, ty = tid >> 5;
    int row0 = blockIdx.x * 32;
    if (tid < IN_DIM) sigf[tid] = 1.0f / (1.0f + __expf(-fi[tid]));

    float acc[4][4];
    #pragma unroll
    for (int j = 0; j < 4; j++)
        #pragma unroll
        for (int i = 0; i < 4; i++) acc[j][i] = 0.0f;

    for (int kc = 0; kc < 4; kc++) {
        __syncthreads();
        #pragma unroll
        for (int i = 0; i < 8; i++) {  // xs: 32 rows x 64 k
            int e = tid + i * 256;
            int r = e >> 6, kk = e & 63;
            int row = row0 + r;
            int k = kc * 64 + kk;
            xs[e] = (row < N_NODES) ? x[row * IN_DIM + k] * sigf[k] : 0.0f;
        }
        #pragma unroll
        for (int i = 0; i < 32; i++) { // ws: 64 k x 128 c
            int e = tid + i * 256;
            int kk = e >> 7, c = e & 127;
            ws[e] = W1[(kc * 64 + kk) * HID + c];
        }
        __syncthreads();
        #pragma unroll 4
        for (int kk = 0; kk < 64; kk++) {
            float4 w4 = *(const float4*)&ws[kk * 128 + tx * 4];
            #pragma unroll
            for (int j = 0; j < 4; j++) {
                float xv = xs[(ty + j * 8) * 64 + kk];
                acc[j][0] += xv * w4.x;
                acc[j][1] += xv * w4.y;
                acc[j][2] += xv * w4.z;
                acc[j][3] += xv * w4.w;
            }
        }
    }

    float4 aS = *(const float4*)&attS[tx * 4];
    float4 aD = *(const float4*)&attD[tx * 4];
    #pragma unroll
    for (int j = 0; j < 4; j++) {
        int row = row0 + ty + j * 8;
        float4 v = make_float4(acc[j][0], acc[j][1], acc[j][2], acc[j][3]);
        float ps = v.x * aS.x + v.y * aS.y + v.z * aS.z + v.w * aS.w;
        float pd = v.x * aD.x + v.y * aD.y + v.z * aD.z + v.w * aD.w;
        // reduce over the 8 lanes of each head (32 cols / 4 per lane)
        #pragma unroll
        for (int o = 1; o < 8; o <<= 1) {
            ps += __shfl_xor_sync(0xffffffffu, ps, o);
            pd += __shfl_xor_sync(0xffffffffu, pd, o);
        }
        if (row < N_NODES) {
            *(float4*)&g_xp1[row * HID + tx * 4] = v;
            if ((tx & 7) == 0) {
                g_as1[row * HEADS + (tx >> 3)] = ps;
                g_ad1[row * HEADS + (tx >> 3)] = pd;
            }
        }
    }
}

// ---------------- layer-1 gather + softmax + elu + layer-2 projection --------
__global__ __launch_bounds__(256) void gather1_k(
    const float* __restrict__ b1, const float* __restrict__ W2,
    const float* __restrict__ aS2, const float* __restrict__ aD2)
{
    int gw = (blockIdx.x * blockDim.x + threadIdx.x) >> 5;
    int l = threadIdx.x & 31;
    if (gw >= N_NODES) return;
    int rs = g_rowstart[gw], re = g_rowstart[gw + 1];
    float4 ad = *(const float4*)&g_ad1[gw * 4];

    // pass 1: per-head segment max (lanes stride edges)
    float m0 = -1e30f, m1 = -1e30f, m2 = -1e30f, m3 = -1e30f;
    for (int j = rs + l; j < re; j += 32) {
        int s = __ldg(&g_srcs[j]);
        float4 a = *(const float4*)&g_as1[s * 4];
        float e;
        e = a.x + ad.x; e = e > 0.f ? e : NEG_SLOPE * e; m0 = fmaxf(m0, e);
        e = a.y + ad.y; e = e > 0.f ? e : NEG_SLOPE * e; m1 = fmaxf(m1, e);
        e = a.z + ad.z; e = e > 0.f ? e : NEG_SLOPE * e; m2 = fmaxf(m2, e);
        e = a.w + ad.w; e = e > 0.f ? e : NEG_SLOPE * e; m3 = fmaxf(m3, e);
    }
    #pragma unroll
    for (int o = 16; o > 0; o >>= 1) {
        m0 = fmaxf(m0, __shfl_xor_sync(0xffffffffu, m0, o));
        m1 = fmaxf(m1, __shfl_xor_sync(0xffffffffu, m1, o));
        m2 = fmaxf(m2, __shfl_xor_sync(0xffffffffu, m2, o));
        m3 = fmaxf(m3, __shfl_xor_sync(0xffffffffu, m3, o));
    }

    // pass 2: weighted accumulation; lane l owns channels l, 32+l, 64+l, 96+l
    float z0 = 0.f, z1 = 0.f, z2 = 0.f, z3 = 0.f;
    float c0 = 0.f, c1 = 0.f, c2 = 0.f, c3 = 0.f;
    for (int j = rs; j < re; j++) {
        int s = g_srcs[j];                          // broadcast
        float4 a = *(const float4*)&g_as1[s * 4];   // broadcast
        const float* row = g_xp1 + s * HID;
        float e, w;
        e = a.x + ad.x; e = e > 0.f ? e : NEG_SLOPE * e; w = __expf(e - m0);
        z0 += w; c0 += w * row[l];
        e = a.y + ad.y; e = e > 0.f ? e : NEG_SLOPE * e; w = __expf(e - m1);
        z1 += w; c1 += w * row[32 + l];
        e = a.z + ad.z; e = e > 0.f ? e : NEG_SLOPE * e; w = __expf(e - m2);
        z2 += w; c2 += w * row[64 + l];
        e = a.w + ad.w; e = e > 0.f ? e : NEG_SLOPE * e; w = __expf(e - m3);
        z3 += w; c3 += w * row[96 + l];
    }

    float h0 = c0 / (z0 + 1e-16f) + b1[l];
    float h1 = c1 / (z1 + 1e-16f) + b1[32 + l];
    float h2 = c2 / (z2 + 1e-16f) + b1[64 + l];
    float h3 = c3 / (z3 + 1e-16f) + b1[96 + l];
    h0 = h0 > 0.f ? h0 : expm1f(h0);
    h1 = h1 > 0.f ? h1 : expm1f(h1);
    h2 = h2 > 0.f ? h2 : expm1f(h2);
    h3 = h3 > 0.f ? h3 : expm1f(h3);

    // layer-2 projection: xp2 = h @ W2  (W2: [128,2] row-major)
    float p0 = h0 * W2[l * 2]            + h1 * W2[(32 + l) * 2]
             + h2 * W2[(64 + l) * 2]     + h3 * W2[(96 + l) * 2];
    float p1 = h0 * W2[l * 2 + 1]        + h1 * W2[(32 + l) * 2 + 1]
             + h2 * W2[(64 + l) * 2 + 1] + h3 * W2[(96 + l) * 2 + 1];
    #pragma unroll
    for (int o = 16; o > 0; o >>= 1) {
        p0 += __shfl_xor_sync(0xffffffffu, p0, o);
        p1 += __shfl_xor_sync(0xffffffffu, p1, o);
    }
    if (l == 0) {
        g_xp2[gw * 2]     = p0;
        g_xp2[gw * 2 + 1] = p1;
        g_as2[gw] = p0 * aS2[0] + p1 * aS2[1];
        g_ad2[gw] = p0 * aD2[0] + p1 * aD2[1];
    }
}

// ---------------- layer-2 gather + softmax + output --------------------------
__global__ __launch_bounds__(256) void gather2_k(
    const float* __restrict__ b2, float* __restrict__ out)
{
    int gw = (blockIdx.x * blockDim.x + threadIdx.x) >> 5;
    int l = threadIdx.x & 31;
    if (gw >= N_NODES) return;
    int rs = g_rowstart[gw], re = g_rowstart[gw + 1];
    float adn = g_ad2[gw];

    float m = -1e30f;
    for (int j = rs + l; j < re; j += 32) {
        int s = __ldg(&g_srcs[j]);
        float e = g_as2[s] + adn;
        e = e > 0.f ? e : NEG_SLOPE * e;
        m = fmaxf(m, e);
    }
    #pragma unroll
    for (int o = 16; o > 0; o >>= 1)
        m = fmaxf(m, __shfl_xor_sync(0xffffffffu, m, o));

    float z = 0.f, a0 = 0.f, a1 = 0.f;
    for (int j = rs + l; j < re; j += 32) {
        int s = __ldg(&g_srcs[j]);
        float e = g_as2[s] + adn;
        e = e > 0.f ? e : NEG_SLOPE * e;
        float w = __expf(e - m);
        float2 v = *(const float2*)&g_xp2[s * 2];
        z += w; a0 += w * v.x; a1 += w * v.y;
    }
    #pragma unroll
    for (int o = 16; o > 0; o >>= 1) {
        z  += __shfl_xor_sync(0xffffffffu, z, o);
        a0 += __shfl_xor_sync(0xffffffffu, a0, o);
        a1 += __shfl_xor_sync(0xffffffffu, a1, o);
    }
    if (l == 0) {
        float inv = 1.0f / (z + 1e-16f);
        out[gw * 2]     = a0 * inv + b2[0];
        out[gw * 2 + 1] = a1 * inv + b2[1];
    }
}

// ---------------- launch ------------------------------------------------------
extern "C" void kernel_launch(void* const* d_in, const int* in_sizes, int n_in,
                              void* d_out, int out_size) {
    const float* x     = (const float*)d_in[0];
    const float* fi    = (const float*)d_in[1];
    const float* W1    = (const float*)d_in[2];
    const float* attS1 = (const float*)d_in[3];
    const float* attD1 = (const float*)d_in[4];
    const float* b1    = (const float*)d_in[5];
    const float* W2    = (const float*)d_in[6];
    const float* attS2 = (const float*)d_in[7];
    const float* attD2 = (const float*)d_in[8];
    const float* b2    = (const float*)d_in[9];
    const void*  ei    = (const void*)d_in[10];
    float* out = (float*)d_out;

    detect_k<<<1, 1>>>((const int*)ei);

    // GEMM is independent of CSR build.
    gemm_k<<<(N_NODES + 31) / 32, 256>>>(x, fi, W1, attS1, attD1);

    zero_cnt_k<<<(N_NODES + 255) / 256, 256>>>();
    count_k<<<(E_TOT + 255) / 256, 256>>>(ei);
    scan_k<<<1, 1024>>>();
    scatter_k<<<(E_TOT + 255) / 256, 256>>>(ei);

    gather1_k<<<(N_NODES * 32 + 255) / 256, 256>>>(b1, W2, attS2, attD2);
    gather2_k<<<(N_NODES * 32 + 255) / 256, 256>>>(b2, out);
}

// round 3
// speedup vs baseline: 1.2500x; 1.2500x over previous
#include <cuda_runtime.h>
#include <cuda_fp16.h>
#include <math.h>

#define N_NODES 50000
#define N_EDGES 1600000
#define E_TOT   (N_EDGES + N_NODES)
#define IN_DIM  256
#define HID     128
#define HEADS   4
#define OUT_DIM 2
#define NEG_SLOPE 0.2f

// ---------------- device scratch ---------------------------------------------
__device__ __half  g_xp1h[N_NODES * HID];   // layer-1 projected features (fp16)
__device__ float   g_as1[N_NODES * HEADS];
__device__ float   g_ad1[N_NODES * HEADS];
__device__ float4  g_ew[E_TOT];             // per-edge softmax numerators (4 heads)
__device__ float4  g_n2[N_NODES];           // (p0, p1, as2, ad2)
__device__ int     g_cnt[N_NODES];
__device__ int     g_rowstart[N_NODES + 1];
__device__ int     g_cursor[N_NODES];
__device__ int     g_srcs[E_TOT];
__device__ int     g_is64;

__device__ __forceinline__ float leaky(float e) {
    return e > 0.f ? e : NEG_SLOPE * e;
}
__device__ __forceinline__ unsigned pack_half2(float a, float b) {
    __half2 h = __floats2half2_rn(a, b);
    return *(unsigned*)&h;
}

// ---------------- init: zero counts + dtype probe -----------------------------
__global__ void init_k(const int* __restrict__ ei32) {
    int i = blockIdx.x * blockDim.x + threadIdx.x;
    if (i < N_NODES) g_cnt[i] = 0;
    if (i == 0) {
        int all0 = 1;
        for (int k = 0; k < 64; k++)
            if (ei32[2 * k + 1] != 0) all0 = 0;
        g_is64 = all0;   // int64 node ids < 50000 -> odd words all zero
    }
}

// ---------------- layer-1 GEMM: 128x128 tile, 8x8 micro-tile ------------------
__global__ __launch_bounds__(256, 2) void gemm_k(
    const float* __restrict__ x, const float* __restrict__ fi,
    const float* __restrict__ W1,
    const float* __restrict__ attS, const float* __restrict__ attD)
{
    const int S = 132;                  // padded row stride for xs (floats)
    __shared__ float xs[32 * S];        // [kk][row] transposed
    __shared__ float ws[32 * 128];      // [kk][col]
    __shared__ float sigf[IN_DIM];
    int tid = threadIdx.x;
    int tx = tid & 15, ty = tid >> 4;
    int row0 = blockIdx.x * 128;

    sigf[tid] = 1.0f / (1.0f + __expf(-fi[tid]));
    __syncthreads();

    float acc[8][8];
    #pragma unroll
    for (int r = 0; r < 8; r++)
        #pragma unroll
        for (int c = 0; c < 8; c++) acc[r][c] = 0.0f;

    int srow = tid >> 3;          // 0..31
    int q    = tid & 7;           // 0..7  (k-quad)

    for (int k0 = 0; k0 < IN_DIM; k0 += 32) {
        // stage xs: 128 rows x 32 k, transposed, scaled by sigmoid(fi)
        float4 sg = *(const float4*)&sigf[k0 + 4 * q];
        #pragma unroll
        for (int p = 0; p < 4; p++) {
            int row = srow + p * 32;
            int grow = row0 + row;
            float4 v = make_float4(0.f, 0.f, 0.f, 0.f);
            if (grow < N_NODES) v = *(const float4*)&x[grow * IN_DIM + k0 + 4 * q];
            xs[(4 * q + 0) * S + row] = v.x * sg.x;
            xs[(4 * q + 1) * S + row] = v.y * sg.y;
            xs[(4 * q + 2) * S + row] = v.z * sg.z;
            xs[(4 * q + 3) * S + row] = v.w * sg.w;
        }
        // stage ws: 32 k x 128 cols (W1 already k-major)
        #pragma unroll
        for (int p = 0; p < 4; p++) {
            int kk = (tid >> 5) + p * 8;
            int c = (tid & 31) * 4;
            *(float4*)&ws[kk * 128 + c] = *(const float4*)&W1[(k0 + kk) * HID + c];
        }
        __syncthreads();

        #pragma unroll
        for (int kk = 0; kk < 32; kk++) {
            float4 a0 = *(float4*)&xs[kk * S + 4 * ty];
            float4 a1 = *(float4*)&xs[kk * S + 64 + 4 * ty];
            float4 b0 = *(float4*)&ws[kk * 128 + 4 * tx];
            float4 b1 = *(float4*)&ws[kk * 128 + 64 + 4 * tx];
            float av[8] = {a0.x, a0.y, a0.z, a0.w, a1.x, a1.y, a1.z, a1.w};
            float bv[8] = {b0.x, b0.y, b0.z, b0.w, b1.x, b1.y, b1.z, b1.w};
            #pragma unroll
            for (int r = 0; r < 8; r++)
                #pragma unroll
                for (int c = 0; c < 8; c++)
                    acc[r][c] += av[r] * bv[c];
        }
        __syncthreads();
    }

    // epilogue: store fp16 features + fp32 attention logits
    float4 asL = *(const float4*)&attS[4 * tx];
    float4 asH = *(const float4*)&attS[64 + 4 * tx];
    float4 adL = *(const float4*)&attD[4 * tx];
    float4 adH = *(const float4*)&attD[64 + 4 * tx];

    #pragma unroll
    for (int r = 0; r < 8; r++) {
        int grow = row0 + ((r < 4) ? 4 * ty + r : 64 + 4 * ty + (r - 4));
        float psL = acc[r][0]*asL.x + acc[r][1]*asL.y + acc[r][2]*asL.z + acc[r][3]*asL.w;
        float psH = acc[r][4]*asH.x + acc[r][5]*asH.y + acc[r][6]*asH.z + acc[r][7]*asH.w;
        float pdL = acc[r][0]*adL.x + acc[r][1]*adL.y + acc[r][2]*adL.z + acc[r][3]*adL.w;
        float pdH = acc[r][4]*adH.x + acc[r][5]*adH.y + acc[r][6]*adH.z + acc[r][7]*adH.w;
        #pragma unroll
        for (int o = 1; o < 8; o <<= 1) {
            psL += __shfl_xor_sync(0xffffffffu, psL, o);
            psH += __shfl_xor_sync(0xffffffffu, psH, o);
            pdL += __shfl_xor_sync(0xffffffffu, pdL, o);
            pdH += __shfl_xor_sync(0xffffffffu, pdH, o);
        }
        if (grow < N_NODES) {
            uint2 lo = make_uint2(pack_half2(acc[r][0], acc[r][1]),
                                  pack_half2(acc[r][2], acc[r][3]));
            uint2 hi = make_uint2(pack_half2(acc[r][4], acc[r][5]),
                                  pack_half2(acc[r][6], acc[r][7]));
            *(uint2*)&g_xp1h[grow * HID + 4 * tx]      = lo;
            *(uint2*)&g_xp1h[grow * HID + 64 + 4 * tx] = hi;
            if ((tx & 7) == 0) {
                int hA = tx >> 3;                       // 0 or 1
                g_as1[grow * 4 + hA]     = psL;
                g_as1[grow * 4 + hA + 2] = psH;
                g_ad1[grow * 4 + hA]     = pdL;
                g_ad1[grow * 4 + hA + 2] = pdH;
            }
        }
    }
}

// ---------------- CSR build ----------------------------------------------------
__global__ void count_k(const void* __restrict__ eiv) {
    int i = blockIdx.x * blockDim.x + threadIdx.x;
    if (i >= E_TOT) return;
    int dst;
    if (i < N_EDGES) {
        if (g_is64) dst = (int)((const long long*)eiv)[N_EDGES + i];
        else        dst = ((const int*)eiv)[N_EDGES + i];
    } else dst = i - N_EDGES;
    atomicAdd(&g_cnt[dst], 1);
}

__global__ void scan_k() {
    const int CH = 49;
    int t = threadIdx.x;
    int base = t * CH;
    int tot = 0;
    for (int j = 0; j < CH; j++) {
        int idx = base + j;
        if (idx < N_NODES) tot += g_cnt[idx];
    }
    __shared__ int wsum[32];
    int lane = t & 31, wid = t >> 5;
    int xincl = tot;
    #pragma unroll
    for (int o = 1; o < 32; o <<= 1) {
        int y = __shfl_up_sync(0xffffffffu, xincl, o);
        if (lane >= o) xincl += y;
    }
    if (lane == 31) wsum[wid] = xincl;
    __syncthreads();
    if (wid == 0) {
        int v = wsum[lane];
        #pragma unroll
        for (int o = 1; o < 32; o <<= 1) {
            int y = __shfl_up_sync(0xffffffffu, v, o);
            if (lane >= o) v += y;
        }
        wsum[lane] = v;
    }
    __syncthreads();
    int run = xincl - tot + (wid > 0 ? wsum[wid - 1] : 0);
    for (int j = 0; j < CH; j++) {
        int idx = base + j;
        if (idx < N_NODES) {
            g_rowstart[idx] = run;
            g_cursor[idx]   = run;
            run += g_cnt[idx];
        }
    }
    if (t == 1023) g_rowstart[N_NODES] = run;
}

// scatter + per-edge softmax numerators (no max subtraction: logits bounded)
__global__ void scatter_k(const void* __restrict__ eiv) {
    int i = blockIdx.x * blockDim.x + threadIdx.x;
    if (i >= E_TOT) return;
    int src, dst;
    if (i < N_EDGES) {
        if (g_is64) {
            const long long* e = (const long long*)eiv;
            src = (int)e[i]; dst = (int)e[N_EDGES + i];
        } else {
            const int* e = (const int*)eiv;
            src = e[i]; dst = e[N_EDGES + i];
        }
    } else src = dst = i - N_EDGES;
    int p = atomicAdd(&g_cursor[dst], 1);
    g_srcs[p] = src;
    float4 a  = *(const float4*)&g_as1[src * 4];
    float4 ad = *(const float4*)&g_ad1[dst * 4];
    g_ew[p] = make_float4(__expf(leaky(a.x + ad.x)),
                          __expf(leaky(a.y + ad.y)),
                          __expf(leaky(a.z + ad.z)),
                          __expf(leaky(a.w + ad.w)));
}

// ---------------- layer-1 gather + elu + layer-2 projection -------------------
// One warp per dst node. Lane l owns channels 4l..4l+3 (all in head l/8).
__global__ __launch_bounds__(256) void gather1_k(
    const float* __restrict__ b1, const float* __restrict__ W2,
    const float* __restrict__ aS2, const float* __restrict__ aD2)
{
    int gw = (blockIdx.x * blockDim.x + threadIdx.x) >> 5;
    int l = threadIdx.x & 31;
    if (gw >= N_NODES) return;
    int rs = g_rowstart[gw], re = g_rowstart[gw + 1];

    float z = 0.f, c0 = 0.f, c1 = 0.f, c2 = 0.f, c3 = 0.f;
    bool hiPair = (l & 16), hiOne = (l & 8);

    #pragma unroll 2
    for (int j = rs; j < re; j++) {
        int s = __ldg(&g_srcs[j]);                  // broadcast
        float4 w4 = __ldg(&g_ew[j]);                // broadcast
        float wv = hiPair ? (hiOne ? w4.w : w4.z) : (hiOne ? w4.y : w4.x);
        uint2 pk = *(const uint2*)&g_xp1h[s * HID + 4 * l];   // coalesced 256B/warp
        float2 f0 = __half22float2(*(__half2*)&pk.x);
        float2 f1 = __half22float2(*(__half2*)&pk.y);
        z  += wv;
        c0 += wv * f0.x; c1 += wv * f0.y;
        c2 += wv * f1.x; c3 += wv * f1.y;
    }

    float inv = 1.0f / (z + 1e-16f);
    float4 bb = *(const float4*)&b1[4 * l];
    float h0 = c0 * inv + bb.x;
    float h1 = c1 * inv + bb.y;
    float h2 = c2 * inv + bb.z;
    float h3 = c3 * inv + bb.w;
    h0 = h0 > 0.f ? h0 : expm1f(h0);
    h1 = h1 > 0.f ? h1 : expm1f(h1);
    h2 = h2 > 0.f ? h2 : expm1f(h2);
    h3 = h3 > 0.f ? h3 : expm1f(h3);

    float4 wa = *(const float4*)&W2[8 * l];        // rows 4l, 4l+1
    float4 wb = *(const float4*)&W2[8 * l + 4];    // rows 4l+2, 4l+3
    float p0 = h0 * wa.x + h1 * wa.z + h2 * wb.x + h3 * wb.z;
    float p1 = h0 * wa.y + h1 * wa.w + h2 * wb.y + h3 * wb.w;
    #pragma unroll
    for (int o = 16; o > 0; o >>= 1) {
        p0 += __shfl_xor_sync(0xffffffffu, p0, o);
        p1 += __shfl_xor_sync(0xffffffffu, p1, o);
    }
    if (l == 0) {
        float as2 = p0 * aS2[0] + p1 * aS2[1];
        float ad2 = p0 * aD2[0] + p1 * aD2[1];
        g_n2[gw] = make_float4(p0, p1, as2, ad2);
    }
}

// ---------------- layer-2 gather + output -------------------------------------
__global__ __launch_bounds__(256) void gather2_k(
    const float* __restrict__ b2, float* __restrict__ out)
{
    int gw = (blockIdx.x * blockDim.x + threadIdx.x) >> 5;
    int l = threadIdx.x & 31;
    if (gw >= N_NODES) return;
    int rs = g_rowstart[gw], re = g_rowstart[gw + 1];
    float ad = g_n2[gw].w;

    float z = 0.f, a0 = 0.f, a1 = 0.f;
    for (int j = rs + l; j < re; j += 32) {
        int s = __ldg(&g_srcs[j]);
        float4 n = __ldg(&g_n2[s]);
        float w = __expf(leaky(n.z + ad));
        z += w; a0 += w * n.x; a1 += w * n.y;
    }
    #pragma unroll
    for (int o = 16; o > 0; o >>= 1) {
        z  += __shfl_xor_sync(0xffffffffu, z, o);
        a0 += __shfl_xor_sync(0xffffffffu, a0, o);
        a1 += __shfl_xor_sync(0xffffffffu, a1, o);
    }
    if (l == 0) {
        float inv = 1.0f / (z + 1e-16f);
        out[gw * 2]     = a0 * inv + b2[0];
        out[gw * 2 + 1] = a1 * inv + b2[1];
    }
}

// ---------------- launch --------------------------------------------------------
extern "C" void kernel_launch(void* const* d_in, const int* in_sizes, int n_in,
                              void* d_out, int out_size) {
    const float* x     = (const float*)d_in[0];
    const float* fi    = (const float*)d_in[1];
    const float* W1    = (const float*)d_in[2];
    const float* attS1 = (const float*)d_in[3];
    const float* attD1 = (const float*)d_in[4];
    const float* b1    = (const float*)d_in[5];
    const float* W2    = (const float*)d_in[6];
    const float* attS2 = (const float*)d_in[7];
    const float* attD2 = (const float*)d_in[8];
    const float* b2    = (const float*)d_in[9];
    const void*  ei    = (const void*)d_in[10];
    float* out = (float*)d_out;

    init_k<<<(N_NODES + 255) / 256, 256>>>((const int*)ei);
    gemm_k<<<(N_NODES + 127) / 128, 256>>>(x, fi, W1, attS1, attD1);
    count_k<<<(E_TOT + 255) / 256, 256>>>(ei);
    scan_k<<<1, 1024>>>();
    scatter_k<<<(E_TOT + 255) / 256, 256>>>(ei);
    gather1_k<<<(N_NODES * 32 + 255) / 256, 256>>>(b1, W2, attS2, attD2);
    gather2_k<<<(N_NODES * 32 + 255) / 256, 256>>>(b2, out);
}

// round 4
// speedup vs baseline: 1.6818x; 1.3455x over previous
#include <cuda_runtime.h>
#include <cuda_fp16.h>
#include <math.h>

#define N_NODES 50000
#define N_EDGES 1600000
#define E_TOT   (N_EDGES + N_NODES)
#define IN_DIM  256
#define HID     128
#define HEADS   4
#define OUT_DIM 2
#define NEG_SLOPE 0.2f
#define NB_SCAN ((N_NODES + 255) / 256)   // 196 scan blocks

// ---------------- device scratch ---------------------------------------------
__device__ __half  g_xp1h[N_NODES * HID];   // layer-1 projected features (fp16)
__device__ float   g_as1[N_NODES * HEADS];
__device__ float   g_ad1[N_NODES * HEADS];
__device__ float4  g_ew[E_TOT];             // per-edge softmax numerators (4 heads)
__device__ float4  g_n2[N_NODES];           // (p0, p1, as2, ad2)
__device__ int     g_cnt[N_NODES];
__device__ int     g_excl[N_NODES];         // per-block exclusive scans
__device__ int     g_bsum[NB_SCAN];         // block totals -> block offsets
__device__ int     g_rowstart[N_NODES + 1];
__device__ int     g_cursor[N_NODES];
__device__ int     g_srcs[E_TOT];
__device__ int     g_is64;

__device__ __forceinline__ float leaky(float e) {
    return e > 0.f ? e : NEG_SLOPE * e;
}
__device__ __forceinline__ unsigned pack_half2(float a, float b) {
    __half2 h = __floats2half2_rn(a, b);
    return *(unsigned*)&h;
}

// inclusive scan of v across a 256-thread block; returns inclusive value.
__device__ __forceinline__ int block_scan_incl_256(int v, int* smem8) {
    int lane = threadIdx.x & 31, wid = threadIdx.x >> 5;
    int x = v;
    #pragma unroll
    for (int o = 1; o < 32; o <<= 1) {
        int y = __shfl_up_sync(0xffffffffu, x, o);
        if (lane >= o) x += y;
    }
    if (lane == 31) smem8[wid] = x;
    __syncthreads();
    if (wid == 0 && lane < 8) {
        int w = smem8[lane];
        #pragma unroll
        for (int o = 1; o < 8; o <<= 1) {
            int y = __shfl_up_sync(0xffu, w, o);
            if (lane >= o) w += y;
        }
        smem8[lane] = w;
    }
    __syncthreads();
    if (wid > 0) x += smem8[wid - 1];
    return x;
}

// ---------------- init: zero counts + dtype probe -----------------------------
__global__ void init_k(const int* __restrict__ ei32) {
    int i = blockIdx.x * blockDim.x + threadIdx.x;
    if (i < N_NODES) g_cnt[i] = 0;
    if (i == 0) {
        int all0 = 1;
        for (int k = 0; k < 64; k++)
            if (ei32[2 * k + 1] != 0) all0 = 0;
        g_is64 = all0;   // int64 node ids < 50000 -> odd words all zero
    }
}

// ---------------- layer-1 GEMM: 128x128 tile, 8x8 micro-tile ------------------
__global__ __launch_bounds__(256, 2) void gemm_k(
    const float* __restrict__ x, const float* __restrict__ fi,
    const float* __restrict__ W1,
    const float* __restrict__ attS, const float* __restrict__ attD)
{
    const int S = 132;                  // padded row stride for xs (floats)
    __shared__ float xs[32 * S];        // [kk][row] transposed
    __shared__ float ws[32 * 128];      // [kk][col]
    __shared__ float sigf[IN_DIM];
    int tid = threadIdx.x;
    int tx = tid & 15, ty = tid >> 4;
    int row0 = blockIdx.x * 128;

    sigf[tid] = 1.0f / (1.0f + __expf(-fi[tid]));
    __syncthreads();

    float acc[8][8];
    #pragma unroll
    for (int r = 0; r < 8; r++)
        #pragma unroll
        for (int c = 0; c < 8; c++) acc[r][c] = 0.0f;

    int srow = tid >> 3;          // 0..31
    int q    = tid & 7;           // 0..7  (k-quad)

    for (int k0 = 0; k0 < IN_DIM; k0 += 32) {
        float4 sg = *(const float4*)&sigf[k0 + 4 * q];
        #pragma unroll
        for (int p = 0; p < 4; p++) {
            int row = srow + p * 32;
            int grow = row0 + row;
            float4 v = make_float4(0.f, 0.f, 0.f, 0.f);
            if (grow < N_NODES) v = *(const float4*)&x[grow * IN_DIM + k0 + 4 * q];
            xs[(4 * q + 0) * S + row] = v.x * sg.x;
            xs[(4 * q + 1) * S + row] = v.y * sg.y;
            xs[(4 * q + 2) * S + row] = v.z * sg.z;
            xs[(4 * q + 3) * S + row] = v.w * sg.w;
        }
        #pragma unroll
        for (int p = 0; p < 4; p++) {
            int kk = (tid >> 5) + p * 8;
            int c = (tid & 31) * 4;
            *(float4*)&ws[kk * 128 + c] = *(const float4*)&W1[(k0 + kk) * HID + c];
        }
        __syncthreads();

        #pragma unroll
        for (int kk = 0; kk < 32; kk++) {
            float4 a0 = *(float4*)&xs[kk * S + 4 * ty];
            float4 a1 = *(float4*)&xs[kk * S + 64 + 4 * ty];
            float4 b0 = *(float4*)&ws[kk * 128 + 4 * tx];
            float4 b1 = *(float4*)&ws[kk * 128 + 64 + 4 * tx];
            float av[8] = {a0.x, a0.y, a0.z, a0.w, a1.x, a1.y, a1.z, a1.w};
            float bv[8] = {b0.x, b0.y, b0.z, b0.w, b1.x, b1.y, b1.z, b1.w};
            #pragma unroll
            for (int r = 0; r < 8; r++)
                #pragma unroll
                for (int c = 0; c < 8; c++)
                    acc[r][c] += av[r] * bv[c];
        }
        __syncthreads();
    }

    float4 asL = *(const float4*)&attS[4 * tx];
    float4 asH = *(const float4*)&attS[64 + 4 * tx];
    float4 adL = *(const float4*)&attD[4 * tx];
    float4 adH = *(const float4*)&attD[64 + 4 * tx];

    #pragma unroll
    for (int r = 0; r < 8; r++) {
        int grow = row0 + ((r < 4) ? 4 * ty + r : 64 + 4 * ty + (r - 4));
        float psL = acc[r][0]*asL.x + acc[r][1]*asL.y + acc[r][2]*asL.z + acc[r][3]*asL.w;
        float psH = acc[r][4]*asH.x + acc[r][5]*asH.y + acc[r][6]*asH.z + acc[r][7]*asH.w;
        float pdL = acc[r][0]*adL.x + acc[r][1]*adL.y + acc[r][2]*adL.z + acc[r][3]*adL.w;
        float pdH = acc[r][4]*adH.x + acc[r][5]*adH.y + acc[r][6]*adH.z + acc[r][7]*adH.w;
        #pragma unroll
        for (int o = 1; o < 8; o <<= 1) {
            psL += __shfl_xor_sync(0xffffffffu, psL, o);
            psH += __shfl_xor_sync(0xffffffffu, psH, o);
            pdL += __shfl_xor_sync(0xffffffffu, pdL, o);
            pdH += __shfl_xor_sync(0xffffffffu, pdH, o);
        }
        if (grow < N_NODES) {
            uint2 lo = make_uint2(pack_half2(acc[r][0], acc[r][1]),
                                  pack_half2(acc[r][2], acc[r][3]));
            uint2 hi = make_uint2(pack_half2(acc[r][4], acc[r][5]),
                                  pack_half2(acc[r][6], acc[r][7]));
            *(uint2*)&g_xp1h[grow * HID + 4 * tx]      = lo;
            *(uint2*)&g_xp1h[grow * HID + 64 + 4 * tx] = hi;
            if ((tx & 7) == 0) {
                int hA = tx >> 3;
                g_as1[grow * 4 + hA]     = psL;
                g_as1[grow * 4 + hA + 2] = psH;
                g_ad1[grow * 4 + hA]     = pdL;
                g_ad1[grow * 4 + hA + 2] = pdH;
            }
        }
    }
}

// ---------------- CSR build ----------------------------------------------------
__global__ void count_k(const void* __restrict__ eiv) {
    int i = blockIdx.x * blockDim.x + threadIdx.x;
    if (i >= E_TOT) return;
    int dst;
    if (i < N_EDGES) {
        if (g_is64) dst = (int)((const long long*)eiv)[N_EDGES + i];
        else        dst = ((const int*)eiv)[N_EDGES + i];
    } else dst = i - N_EDGES;
    atomicAdd(&g_cnt[dst], 1);
}

// multi-block scan, phase A: per-block exclusive scan + block totals
__global__ __launch_bounds__(256) void scanA_k() {
    __shared__ int smem8[8];
    int i = blockIdx.x * 256 + threadIdx.x;
    int v = (i < N_NODES) ? g_cnt[i] : 0;
    int incl = block_scan_incl_256(v, smem8);
    if (i < N_NODES) g_excl[i] = incl - v;
    if (threadIdx.x == 255) g_bsum[blockIdx.x] = incl;
}

// phase B: one block scans the block totals (exclusive), writes grand total
__global__ __launch_bounds__(256) void scanB_k() {
    __shared__ int smem8[8];
    int t = threadIdx.x;
    int v = (t < NB_SCAN) ? g_bsum[t] : 0;
    int incl = block_scan_incl_256(v, smem8);
    if (t < NB_SCAN) g_bsum[t] = incl - v;
    if (t == NB_SCAN - 1) g_rowstart[N_NODES] = incl;  // == E_TOT
}

// phase C: add block offsets, write rowstart + cursor
__global__ __launch_bounds__(256) void scanC_k() {
    int i = blockIdx.x * 256 + threadIdx.x;
    if (i < N_NODES) {
        int r = g_excl[i] + g_bsum[blockIdx.x];
        g_rowstart[i] = r;
        g_cursor[i]   = r;
    }
}

// scatter + per-edge softmax numerators (no max subtraction: logits bounded)
__global__ void scatter_k(const void* __restrict__ eiv) {
    int i = blockIdx.x * blockDim.x + threadIdx.x;
    if (i >= E_TOT) return;
    int src, dst;
    if (i < N_EDGES) {
        if (g_is64) {
            const long long* e = (const long long*)eiv;
            src = (int)e[i]; dst = (int)e[N_EDGES + i];
        } else {
            const int* e = (const int*)eiv;
            src = e[i]; dst = e[N_EDGES + i];
        }
    } else src = dst = i - N_EDGES;
    int p = atomicAdd(&g_cursor[dst], 1);
    g_srcs[p] = src;
    float4 a  = *(const float4*)&g_as1[src * 4];
    float4 ad = *(const float4*)&g_ad1[dst * 4];
    g_ew[p] = make_float4(__expf(leaky(a.x + ad.x)),
                          __expf(leaky(a.y + ad.y)),
                          __expf(leaky(a.z + ad.z)),
                          __expf(leaky(a.w + ad.w)));
}

// ---------------- layer-1 gather + elu + layer-2 projection -------------------
__global__ __launch_bounds__(256) void gather1_k(
    const float* __restrict__ b1, const float* __restrict__ W2,
    const float* __restrict__ aS2, const float* __restrict__ aD2)
{
    int gw = (blockIdx.x * blockDim.x + threadIdx.x) >> 5;
    int l = threadIdx.x & 31;
    if (gw >= N_NODES) return;
    int rs = g_rowstart[gw], re = g_rowstart[gw + 1];

    float z = 0.f, c0 = 0.f, c1 = 0.f, c2 = 0.f, c3 = 0.f;
    bool hiPair = (l & 16), hiOne = (l & 8);

    #pragma unroll 2
    for (int j = rs; j < re; j++) {
        int s = __ldg(&g_srcs[j]);                  // broadcast
        float4 w4 = __ldg(&g_ew[j]);                // broadcast
        float wv = hiPair ? (hiOne ? w4.w : w4.z) : (hiOne ? w4.y : w4.x);
        uint2 pk = *(const uint2*)&g_xp1h[s * HID + 4 * l];   // coalesced 256B/warp
        float2 f0 = __half22float2(*(__half2*)&pk.x);
        float2 f1 = __half22float2(*(__half2*)&pk.y);
        z  += wv;
        c0 += wv * f0.x; c1 += wv * f0.y;
        c2 += wv * f1.x; c3 += wv * f1.y;
    }

    float inv = 1.0f / (z + 1e-16f);
    float4 bb = *(const float4*)&b1[4 * l];
    float h0 = c0 * inv + bb.x;
    float h1 = c1 * inv + bb.y;
    float h2 = c2 * inv + bb.z;
    float h3 = c3 * inv + bb.w;
    h0 = h0 > 0.f ? h0 : expm1f(h0);
    h1 = h1 > 0.f ? h1 : expm1f(h1);
    h2 = h2 > 0.f ? h2 : expm1f(h2);
    h3 = h3 > 0.f ? h3 : expm1f(h3);

    float4 wa = *(const float4*)&W2[8 * l];
    float4 wb = *(const float4*)&W2[8 * l + 4];
    float p0 = h0 * wa.x + h1 * wa.z + h2 * wb.x + h3 * wb.z;
    float p1 = h0 * wa.y + h1 * wa.w + h2 * wb.y + h3 * wb.w;
    #pragma unroll
    for (int o = 16; o > 0; o >>= 1) {
        p0 += __shfl_xor_sync(0xffffffffu, p0, o);
        p1 += __shfl_xor_sync(0xffffffffu, p1, o);
    }
    if (l == 0) {
        float as2 = p0 * aS2[0] + p1 * aS2[1];
        float ad2 = p0 * aD2[0] + p1 * aD2[1];
        g_n2[gw] = make_float4(p0, p1, as2, ad2);
    }
}

// ---------------- layer-2 gather + output -------------------------------------
__global__ __launch_bounds__(256) void gather2_k(
    const float* __restrict__ b2, float* __restrict__ out)
{
    int gw = (blockIdx.x * blockDim.x + threadIdx.x) >> 5;
    int l = threadIdx.x & 31;
    if (gw >= N_NODES) return;
    int rs = g_rowstart[gw], re = g_rowstart[gw + 1];
    float ad = g_n2[gw].w;

    float z = 0.f, a0 = 0.f, a1 = 0.f;
    for (int j = rs + l; j < re; j += 32) {
        int s = __ldg(&g_srcs[j]);
        float4 n = __ldg(&g_n2[s]);
        float w = __expf(leaky(n.z + ad));
        z += w; a0 += w * n.x; a1 += w * n.y;
    }
    #pragma unroll
    for (int o = 16; o > 0; o >>= 1) {
        z  += __shfl_xor_sync(0xffffffffu, z, o);
        a0 += __shfl_xor_sync(0xffffffffu, a0, o);
        a1 += __shfl_xor_sync(0xffffffffu, a1, o);
    }
    if (l == 0) {
        float inv = 1.0f / (z + 1e-16f);
        out[gw * 2]     = a0 * inv + b2[0];
        out[gw * 2 + 1] = a1 * inv + b2[1];
    }
}

// ---------------- launch --------------------------------------------------------
extern "C" void kernel_launch(void* const* d_in, const int* in_sizes, int n_in,
                              void* d_out, int out_size) {
    const float* x     = (const float*)d_in[0];
    const float* fi    = (const float*)d_in[1];
    const float* W1    = (const float*)d_in[2];
    const float* attS1 = (const float*)d_in[3];
    const float* attD1 = (const float*)d_in[4];
    const float* b1    = (const float*)d_in[5];
    const float* W2    = (const float*)d_in[6];
    const float* attS2 = (const float*)d_in[7];
    const float* attD2 = (const float*)d_in[8];
    const float* b2    = (const float*)d_in[9];
    const void*  ei    = (const void*)d_in[10];
    float* out = (float*)d_out;

    init_k<<<(N_NODES + 255) / 256, 256>>>((const int*)ei);
    gemm_k<<<(N_NODES + 127) / 128, 256>>>(x, fi, W1, attS1, attD1);
    count_k<<<(E_TOT + 255) / 256, 256>>>(ei);
    scanA_k<<<NB_SCAN, 256>>>();
    scanB_k<<<1, 256>>>();
    scanC_k<<<NB_SCAN, 256>>>();
    scatter_k<<<(E_TOT + 255) / 256, 256>>>(ei);
    gather1_k<<<(N_NODES * 32 + 255) / 256, 256>>>(b1, W2, attS2, attD2);
    gather2_k<<<(N_NODES * 32 + 255) / 256, 256>>>(b2, out);
}

// round 6
// speedup vs baseline: 2.0790x; 1.2362x over previous
#include <cuda_runtime.h>
#include <cuda_fp16.h>
#include <math.h>
#include <stdint.h>

#define N_NODES 50000
#define N_EDGES 1600000
#define E_TOT   (N_EDGES + N_NODES)
#define IN_DIM  256
#define HID     128
#define HEADS   4
#define OUT_DIM 2
#define NEG_SLOPE 0.2f
#define NB_SCAN ((N_NODES + 255) / 256)

#define SA 264                      // smem row stride in halves (528B, conflict-free)
#define GEMM_SMEM (2 * 128 * SA * 2)  // A + B tiles = 135168 B

// ---------------- device scratch ---------------------------------------------
__device__ __half  g_xp1h[N_NODES * HID];
__device__ float   g_as1[N_NODES * HEADS];
__device__ float   g_ad1[N_NODES * HEADS];
__device__ float4  g_ew[E_TOT];
__device__ float4  g_n2[N_NODES];
__device__ __half  g_wth[128 * SA];        // W1^T fp16, [n][k], stride SA
__device__ float   g_sigf[IN_DIM];
__device__ int     g_cnt[N_NODES];
__device__ int     g_excl[N_NODES];
__device__ int     g_bsum[NB_SCAN];
__device__ int     g_rowstart[N_NODES + 1];
__device__ int     g_cursor[N_NODES];
__device__ int     g_srcs[E_TOT];
__device__ int     g_is64;

__device__ __forceinline__ float leaky(float e) { return e > 0.f ? e : NEG_SLOPE * e; }

__device__ __forceinline__ int block_scan_incl_256(int v, int* smem8) {
    int lane = threadIdx.x & 31, wid = threadIdx.x >> 5;
    int x = v;
    #pragma unroll
    for (int o = 1; o < 32; o <<= 1) {
        int y = __shfl_up_sync(0xffffffffu, x, o);
        if (lane >= o) x += y;
    }
    if (lane == 31) smem8[wid] = x;
    __syncthreads();
    if (wid == 0 && lane < 8) {
        int w = smem8[lane];
        #pragma unroll
        for (int o = 1; o < 8; o <<= 1) {
            int y = __shfl_up_sync(0xffu, w, o);
            if (lane >= o) w += y;
        }
        smem8[lane] = w;
    }
    __syncthreads();
    if (wid > 0) x += smem8[wid - 1];
    return x;
}

// ---------------- prep: W1^T -> fp16, sigmoid(fi) ------------------------------
__global__ void prep_w_k(const float* __restrict__ W1, const float* __restrict__ fi) {
    int i = blockIdx.x * 256 + threadIdx.x;        // 256*128 = 32768 elems
    if (i < IN_DIM * HID) {
        int k = i >> 7, n = i & 127;
        g_wth[n * SA + k] = __float2half_rn(W1[i]);
    }
    if (i < IN_DIM) g_sigf[i] = 1.0f / (1.0f + __expf(-fi[i]));
}

// ---------------- init: zero counts + dtype probe -----------------------------
__global__ void init_k(const int* __restrict__ ei32) {
    int i = blockIdx.x * blockDim.x + threadIdx.x;
    if (i < N_NODES) g_cnt[i] = 0;
    if (i == 0) {
        int all0 = 1;
        for (int k = 0; k < 64; k++)
            if (ei32[2 * k + 1] != 0) all0 = 0;
        g_is64 = all0;
    }
}

// ---------------- layer-1 GEMM: warp-level mma.sync (fp16 in, fp32 acc) -------
// 128x128 tile/CTA, K=256 fully staged. 8 warps: 2(m) x 4(n), each 64x32.
__global__ __launch_bounds__(256, 1) void gemm_mma_k(
    const float* __restrict__ x,
    const float* __restrict__ attS, const float* __restrict__ attD)
{
    extern __shared__ __half sm[];
    __half* As = sm;                 // [128][SA]
    __half* Bs = sm + 128 * SA;      // [128][SA]  rows = n (W1^T)
    __shared__ float sigf[IN_DIM];
    __shared__ float ssa[HID], ssd[HID];

    int tid = threadIdx.x;
    sigf[tid] = g_sigf[tid];         // tid covers 0..255 = IN_DIM
    if (tid < HID) { ssa[tid] = attS[tid]; ssd[tid] = attD[tid]; }

    // copy pre-converted B (fp16, already [n][k] stride SA) linearly
    {
        const uint4* wsrc = (const uint4*)g_wth;
        uint4* bd = (uint4*)Bs;
        #pragma unroll 4
        for (int i = tid; i < 128 * SA / 8; i += 256) bd[i] = wsrc[i];
    }
    __syncthreads();    // sigf ready

    int row0 = blockIdx.x * 128;
    // stage A: fp32 -> fp16 with sigmoid scale
    for (int f4 = tid; f4 < 8192; f4 += 256) {
        int r = f4 >> 6, c4 = (f4 & 63) * 4;
        int gr = row0 + r;
        float4 v = make_float4(0.f, 0.f, 0.f, 0.f);
        if (gr < N_NODES) v = *(const float4*)&x[(size_t)gr * IN_DIM + c4];
        float4 s = *(float4*)&sigf[c4];
        __half2 h0 = __floats2half2_rn(v.x * s.x, v.y * s.y);
        __half2 h1 = __floats2half2_rn(v.z * s.z, v.w * s.w);
        uint2 u;
        u.x = *(unsigned*)&h0;
        u.y = *(unsigned*)&h1;
        *(uint2*)&As[r * SA + c4] = u;
    }
    __syncthreads();

    int lane = tid & 31, wid = tid >> 5;
    int wm = wid >> 2, wn = wid & 3;
    int r4 = lane >> 2, q = lane & 3;
    int m_base = wm * 64;
    int n_base = wn * 32;

    float c[4][4][4];
    #pragma unroll
    for (int i = 0; i < 4; i++)
        #pragma unroll
        for (int j = 0; j < 4; j++)
            #pragma unroll
            for (int e = 0; e < 4; e++) c[i][j][e] = 0.f;

    const __half* a_base = As + (m_base + r4) * SA + 2 * q;
    const __half* b_base = Bs + (n_base + r4) * SA + 2 * q;

    #pragma unroll 1
    for (int ks = 0; ks < 16; ks++) {
        int k0 = ks * 16;
        unsigned bf[4][2];
        #pragma unroll
        for (int j = 0; j < 4; j++) {
            bf[j][0] = *(const unsigned*)&b_base[j * 8 * SA + k0];
            bf[j][1] = *(const unsigned*)&b_base[j * 8 * SA + k0 + 8];
        }
        #pragma unroll
        for (int i = 0; i < 4; i++) {
            const __half* ap = a_base + i * 16 * SA + k0;
            unsigned a0 = *(const unsigned*)ap;
            unsigned a1 = *(const unsigned*)(ap + 8 * SA);
            unsigned a2 = *(const unsigned*)(ap + 8);
            unsigned a3 = *(const unsigned*)(ap + 8 * SA + 8);
            #pragma unroll
            for (int j = 0; j < 4; j++) {
                asm volatile(
                    "mma.sync.aligned.m16n8k16.row.col.f32.f16.f16.f32 "
                    "{%0,%1,%2,%3}, {%4,%5,%6,%7}, {%8,%9}, {%0,%1,%2,%3};"
                    : "+f"(c[i][j][0]), "+f"(c[i][j][1]),
                      "+f"(c[i][j][2]), "+f"(c[i][j][3])
                    : "r"(a0), "r"(a1), "r"(a2), "r"(a3),
                      "r"(bf[j][0]), "r"(bf[j][1]));
            }
        }
    }
    __syncthreads();   // done with As/Bs; reuse as output stage

    unsigned* stage = (unsigned*)sm;   // [128][68] u32 (fp16x2)
    const int SST = 68;

    #pragma unroll
    for (int i = 0; i < 4; i++) {
        int mr = m_base + i * 16 + r4;       // low row; high = mr+8
        float psl = 0.f, pdl = 0.f, psh = 0.f, pdh = 0.f;
        #pragma unroll
        for (int j = 0; j < 4; j++) {
            int col = n_base + j * 8 + 2 * q;
            float sa0 = ssa[col], sa1 = ssa[col + 1];
            float sd0 = ssd[col], sd1 = ssd[col + 1];
            psl += c[i][j][0] * sa0 + c[i][j][1] * sa1;
            pdl += c[i][j][0] * sd0 + c[i][j][1] * sd1;
            psh += c[i][j][2] * sa0 + c[i][j][3] * sa1;
            pdh += c[i][j][2] * sd0 + c[i][j][3] * sd1;
            // stage fp16 pairs (cols 2q,2q+1 consecutive)
            __half2 lo = __floats2half2_rn(c[i][j][0], c[i][j][1]);
            __half2 hi = __floats2half2_rn(c[i][j][2], c[i][j][3]);
            stage[mr * SST + ((n_base + j * 8) >> 1) + q]       = *(unsigned*)&lo;
            stage[(mr + 8) * SST + ((n_base + j * 8) >> 1) + q] = *(unsigned*)&hi;
        }
        // reduce over quad (covers this warp's 32 cols = head wn)
        #pragma unroll
        for (int o = 1; o < 4; o <<= 1) {
            psl += __shfl_xor_sync(0xffffffffu, psl, o);
            pdl += __shfl_xor_sync(0xffffffffu, pdl, o);
            psh += __shfl_xor_sync(0xffffffffu, psh, o);
            pdh += __shfl_xor_sync(0xffffffffu, pdh, o);
        }
        if (q == 0) {
            int gl = row0 + mr, gh = gl + 8;
            if (gl < N_NODES) { g_as1[gl * 4 + wn] = psl; g_ad1[gl * 4 + wn] = pdl; }
            if (gh < N_NODES) { g_as1[gh * 4 + wn] = psh; g_ad1[gh * 4 + wn] = pdh; }
        }
    }
    __syncthreads();

    // coalesced fp16 writeout
    unsigned* gx = (unsigned*)g_xp1h;
    for (int idx = tid; idx < 128 * 64; idx += 256) {
        int r = idx >> 6, cc = idx & 63;
        int gr = row0 + r;
        if (gr < N_NODES) gx[gr * 64 + cc] = stage[r * SST + cc];
    }
}

// ---------------- CSR build ----------------------------------------------------
__global__ void count_k(const void* __restrict__ eiv) {
    int i = blockIdx.x * blockDim.x + threadIdx.x;
    if (i >= E_TOT) return;
    int dst;
    if (i < N_EDGES) {
        if (g_is64) dst = (int)((const long long*)eiv)[N_EDGES + i];
        else        dst = ((const int*)eiv)[N_EDGES + i];
    } else dst = i - N_EDGES;
    atomicAdd(&g_cnt[dst], 1);
}

__global__ __launch_bounds__(256) void scanA_k() {
    __shared__ int smem8[8];
    int i = blockIdx.x * 256 + threadIdx.x;
    int v = (i < N_NODES) ? g_cnt[i] : 0;
    int incl = block_scan_incl_256(v, smem8);
    if (i < N_NODES) g_excl[i] = incl - v;
    if (threadIdx.x == 255) g_bsum[blockIdx.x] = incl;
}
__global__ __launch_bounds__(256) void scanB_k() {
    __shared__ int smem8[8];
    int t = threadIdx.x;
    int v = (t < NB_SCAN) ? g_bsum[t] : 0;
    int incl = block_scan_incl_256(v, smem8);
    if (t < NB_SCAN) g_bsum[t] = incl - v;
    if (t == NB_SCAN - 1) g_rowstart[N_NODES] = incl;
}
__global__ __launch_bounds__(256) void scanC_k() {
    int i = blockIdx.x * 256 + threadIdx.x;
    if (i < N_NODES) {
        int r = g_excl[i] + g_bsum[blockIdx.x];
        g_rowstart[i] = r;
        g_cursor[i]   = r;
    }
}

__global__ void scatter_k(const void* __restrict__ eiv) {
    int i = blockIdx.x * blockDim.x + threadIdx.x;
    if (i >= E_TOT) return;
    int src, dst;
    if (i < N_EDGES) {
        if (g_is64) {
            const long long* e = (const long long*)eiv;
            src = (int)e[i]; dst = (int)e[N_EDGES + i];
        } else {
            const int* e = (const int*)eiv;
            src = e[i]; dst = e[N_EDGES + i];
        }
    } else src = dst = i - N_EDGES;
    int p = atomicAdd(&g_cursor[dst], 1);
    g_srcs[p] = src;
    float4 a  = *(const float4*)&g_as1[src * 4];
    float4 ad = *(const float4*)&g_ad1[dst * 4];
    g_ew[p] = make_float4(__expf(leaky(a.x + ad.x)),
                          __expf(leaky(a.y + ad.y)),
                          __expf(leaky(a.z + ad.z)),
                          __expf(leaky(a.w + ad.w)));
}

// ---------------- layer-1 gather + elu + layer-2 projection -------------------
__global__ __launch_bounds__(256) void gather1_k(
    const float* __restrict__ b1, const float* __restrict__ W2,
    const float* __restrict__ aS2, const float* __restrict__ aD2)
{
    int gw = (blockIdx.x * blockDim.x + threadIdx.x) >> 5;
    int l = threadIdx.x & 31;
    if (gw >= N_NODES) return;
    int rs = g_rowstart[gw], re = g_rowstart[gw + 1];

    float z = 0.f, c0 = 0.f, c1 = 0.f, c2 = 0.f, c3 = 0.f;
    bool hiPair = (l & 16), hiOne = (l & 8);

    #pragma unroll 2
    for (int j = rs; j < re; j++) {
        int s = __ldg(&g_srcs[j]);
        float4 w4 = __ldg(&g_ew[j]);
        float wv = hiPair ? (hiOne ? w4.w : w4.z) : (hiOne ? w4.y : w4.x);
        uint2 pk = *(const uint2*)&g_xp1h[s * HID + 4 * l];
        float2 f0 = __half22float2(*(__half2*)&pk.x);
        float2 f1 = __half22float2(*(__half2*)&pk.y);
        z  += wv;
        c0 += wv * f0.x; c1 += wv * f0.y;
        c2 += wv * f1.x; c3 += wv * f1.y;
    }

    float inv = 1.0f / (z + 1e-16f);
    float4 bb = *(const float4*)&b1[4 * l];
    float h0 = c0 * inv + bb.x;
    float h1 = c1 * inv + bb.y;
    float h2 = c2 * inv + bb.z;
    float h3 = c3 * inv + bb.w;
    h0 = h0 > 0.f ? h0 : expm1f(h0);
    h1 = h1 > 0.f ? h1 : expm1f(h1);
    h2 = h2 > 0.f ? h2 : expm1f(h2);
    h3 = h3 > 0.f ? h3 : expm1f(h3);

    float4 wa = *(const float4*)&W2[8 * l];
    float4 wb = *(const float4*)&W2[8 * l + 4];
    float p0 = h0 * wa.x + h1 * wa.z + h2 * wb.x + h3 * wb.z;
    float p1 = h0 * wa.y + h1 * wa.w + h2 * wb.y + h3 * wb.w;
    #pragma unroll
    for (int o = 16; o > 0; o >>= 1) {
        p0 += __shfl_xor_sync(0xffffffffu, p0, o);
        p1 += __shfl_xor_sync(0xffffffffu, p1, o);
    }
    if (l == 0) {
        float as2 = p0 * aS2[0] + p1 * aS2[1];
        float ad2 = p0 * aD2[0] + p1 * aD2[1];
        g_n2[gw] = make_float4(p0, p1, as2, ad2);
    }
}

// ---------------- layer-2 gather + output -------------------------------------
__global__ __launch_bounds__(256) void gather2_k(
    const float* __restrict__ b2, float* __restrict__ out)
{
    int gw = (blockIdx.x * blockDim.x + threadIdx.x) >> 5;
    int l = threadIdx.x & 31;
    if (gw >= N_NODES) return;
    int rs = g_rowstart[gw], re = g_rowstart[gw + 1];
    float ad = g_n2[gw].w;

    float z = 0.f, a0 = 0.f, a1 = 0.f;
    for (int j = rs + l; j < re; j += 32) {
        int s = __ldg(&g_srcs[j]);
        float4 n = __ldg(&g_n2[s]);
        float w = __expf(leaky(n.z + ad));
        z += w; a0 += w * n.x; a1 += w * n.y;
    }
    #pragma unroll
    for (int o = 16; o > 0; o >>= 1) {
        z  += __shfl_xor_sync(0xffffffffu, z, o);
        a0 += __shfl_xor_sync(0xffffffffu, a0, o);
        a1 += __shfl_xor_sync(0xffffffffu, a1, o);
    }
    if (l == 0) {
        float inv = 1.0f / (z + 1e-16f);
        out[gw * 2]     = a0 * inv + b2[0];
        out[gw * 2 + 1] = a1 * inv + b2[1];
    }
}

// ---------------- launch --------------------------------------------------------
extern "C" void kernel_launch(void* const* d_in, const int* in_sizes, int n_in,
                              void* d_out, int out_size) {
    const float* x     = (const float*)d_in[0];
    const float* fi    = (const float*)d_in[1];
    const float* W1    = (const float*)d_in[2];
    const float* attS1 = (const float*)d_in[3];
    const float* attD1 = (const float*)d_in[4];
    const float* b1    = (const float*)d_in[5];
    const float* W2    = (const float*)d_in[6];
    const float* attS2 = (const float*)d_in[7];
    const float* attD2 = (const float*)d_in[8];
    const float* b2    = (const float*)d_in[9];
    const void*  ei    = (const void*)d_in[10];
    float* out = (float*)d_out;

    cudaFuncSetAttribute(gemm_mma_k, cudaFuncAttributeMaxDynamicSharedMemorySize, GEMM_SMEM);

    prep_w_k<<<(IN_DIM * HID + 255) / 256, 256>>>(W1, fi);
    init_k<<<(N_NODES + 255) / 256, 256>>>((const int*)ei);
    gemm_mma_k<<<(N_NODES + 127) / 128, 256, GEMM_SMEM>>>(x, attS1, attD1);
    count_k<<<(E_TOT + 255) / 256, 256>>>(ei);
    scanA_k<<<NB_SCAN, 256>>>();
    scanB_k<<<1, 256>>>();
    scanC_k<<<NB_SCAN, 256>>>();
    scatter_k<<<(E_TOT + 255) / 256, 256>>>(ei);
    gather1_k<<<(N_NODES * 32 + 255) / 256, 256>>>(b1, W2, attS2, attD2);
    gather2_k<<<(N_NODES * 32 + 255) / 256, 256>>>(b2, out);
}

// round 7
// speedup vs baseline: 2.1761x; 1.0467x over previous
#include <cuda_runtime.h>
#include <cuda_fp16.h>
#include <math.h>
#include <stdint.h>

#define N_NODES 50000
#define N_EDGES 1600000
#define E_TOT   (N_EDGES + N_NODES)
#define IN_DIM  256
#define HID     128
#define HEADS   4
#define OUT_DIM 2
#define NEG_SLOPE 0.2f
#define NB_SCAN ((N_NODES + 255) / 256)

#define SA 264                        // smem row stride in halves (528B)
#define GEMM_SMEM (2 * 128 * SA * 2)  // A + B tiles = 135168 B

// ---------------- device scratch ---------------------------------------------
__device__ __half  g_xp1h[N_NODES * HID];
__device__ float4  g_as1[N_NODES];         // per-node src logits (4 heads)
__device__ float4  g_ad1[N_NODES];         // per-node dst logits (4 heads)
__device__ float4  g_n2[N_NODES];          // (p0, p1, as2, ad2)
__device__ __half  g_wth[128 * SA];        // W1^T fp16, [n][k], stride SA
__device__ float   g_sigf[IN_DIM];
__device__ int     g_cnt[N_NODES];
__device__ int     g_excl[N_NODES];
__device__ int     g_bsum[NB_SCAN];
__device__ int     g_rowstart[N_NODES + 1];
__device__ int     g_cursor[N_NODES];
__device__ int     g_srcs[E_TOT];
__device__ int     g_is64;

__device__ __forceinline__ float leaky(float e) { return e > 0.f ? e : NEG_SLOPE * e; }

__device__ __forceinline__ int block_scan_incl_256(int v, int* smem8) {
    int lane = threadIdx.x & 31, wid = threadIdx.x >> 5;
    int x = v;
    #pragma unroll
    for (int o = 1; o < 32; o <<= 1) {
        int y = __shfl_up_sync(0xffffffffu, x, o);
        if (lane >= o) x += y;
    }
    if (lane == 31) smem8[wid] = x;
    __syncthreads();
    if (wid == 0 && lane < 8) {
        int w = smem8[lane];
        #pragma unroll
        for (int o = 1; o < 8; o <<= 1) {
            int y = __shfl_up_sync(0xffu, w, o);
            if (lane >= o) w += y;
        }
        smem8[lane] = w;
    }
    __syncthreads();
    if (wid > 0) x += smem8[wid - 1];
    return x;
}

// ---------------- prep: W1^T -> fp16, sigmoid(fi) ------------------------------
__global__ void prep_w_k(const float* __restrict__ W1, const float* __restrict__ fi) {
    int i = blockIdx.x * 256 + threadIdx.x;
    if (i < IN_DIM * HID) {
        int k = i >> 7, n = i & 127;
        g_wth[n * SA + k] = __float2half_rn(W1[i]);
    }
    if (i < IN_DIM) g_sigf[i] = 1.0f / (1.0f + __expf(-fi[i]));
}

// ---------------- init: zero counts + dtype probe -----------------------------
__global__ void init_k(const int* __restrict__ ei32) {
    int i = blockIdx.x * blockDim.x + threadIdx.x;
    if (i < N_NODES) g_cnt[i] = 0;
    if (i == 0) {
        int all0 = 1;
        for (int k = 0; k < 64; k++)
            if (ei32[2 * k + 1] != 0) all0 = 0;
        g_is64 = all0;
    }
}

// ---------------- layer-1 GEMM: warp-level mma.sync ----------------------------
__global__ __launch_bounds__(256, 1) void gemm_mma_k(
    const float* __restrict__ x,
    const float* __restrict__ attS, const float* __restrict__ attD)
{
    extern __shared__ __half sm[];
    __half* As = sm;                 // [128][SA]
    __half* Bs = sm + 128 * SA;      // [128][SA]
    __shared__ float sigf[IN_DIM];
    __shared__ float ssa[HID], ssd[HID];

    int tid = threadIdx.x;
    sigf[tid] = g_sigf[tid];
    if (tid < HID) { ssa[tid] = attS[tid]; ssd[tid] = attD[tid]; }

    {
        const uint4* wsrc = (const uint4*)g_wth;
        uint4* bd = (uint4*)Bs;
        #pragma unroll 4
        for (int i = tid; i < 128 * SA / 8; i += 256) bd[i] = wsrc[i];
    }
    __syncthreads();

    int row0 = blockIdx.x * 128;
    for (int f4 = tid; f4 < 8192; f4 += 256) {
        int r = f4 >> 6, c4 = (f4 & 63) * 4;
        int gr = row0 + r;
        float4 v = make_float4(0.f, 0.f, 0.f, 0.f);
        if (gr < N_NODES) v = *(const float4*)&x[(size_t)gr * IN_DIM + c4];
        float4 s = *(float4*)&sigf[c4];
        __half2 h0 = __floats2half2_rn(v.x * s.x, v.y * s.y);
        __half2 h1 = __floats2half2_rn(v.z * s.z, v.w * s.w);
        uint2 u;
        u.x = *(unsigned*)&h0;
        u.y = *(unsigned*)&h1;
        *(uint2*)&As[r * SA + c4] = u;
    }
    __syncthreads();

    int lane = tid & 31, wid = tid >> 5;
    int wm = wid >> 2, wn = wid & 3;
    int r4 = lane >> 2, q = lane & 3;
    int m_base = wm * 64;
    int n_base = wn * 32;

    float c[4][4][4];
    #pragma unroll
    for (int i = 0; i < 4; i++)
        #pragma unroll
        for (int j = 0; j < 4; j++)
            #pragma unroll
            for (int e = 0; e < 4; e++) c[i][j][e] = 0.f;

    const __half* a_base = As + (m_base + r4) * SA + 2 * q;
    const __half* b_base = Bs + (n_base + r4) * SA + 2 * q;

    #pragma unroll 1
    for (int ks = 0; ks < 16; ks++) {
        int k0 = ks * 16;
        unsigned bf[4][2];
        #pragma unroll
        for (int j = 0; j < 4; j++) {
            bf[j][0] = *(const unsigned*)&b_base[j * 8 * SA + k0];
            bf[j][1] = *(const unsigned*)&b_base[j * 8 * SA + k0 + 8];
        }
        #pragma unroll
        for (int i = 0; i < 4; i++) {
            const __half* ap = a_base + i * 16 * SA + k0;
            unsigned a0 = *(const unsigned*)ap;
            unsigned a1 = *(const unsigned*)(ap + 8 * SA);
            unsigned a2 = *(const unsigned*)(ap + 8);
            unsigned a3 = *(const unsigned*)(ap + 8 * SA + 8);
            #pragma unroll
            for (int j = 0; j < 4; j++) {
                asm volatile(
                    "mma.sync.aligned.m16n8k16.row.col.f32.f16.f16.f32 "
                    "{%0,%1,%2,%3}, {%4,%5,%6,%7}, {%8,%9}, {%0,%1,%2,%3};"
                    : "+f"(c[i][j][0]), "+f"(c[i][j][1]),
                      "+f"(c[i][j][2]), "+f"(c[i][j][3])
                    : "r"(a0), "r"(a1), "r"(a2), "r"(a3),
                      "r"(bf[j][0]), "r"(bf[j][1]));
            }
        }
    }
    __syncthreads();

    unsigned* stage = (unsigned*)sm;
    const int SST = 68;

    #pragma unroll
    for (int i = 0; i < 4; i++) {
        int mr = m_base + i * 16 + r4;
        float psl = 0.f, pdl = 0.f, psh = 0.f, pdh = 0.f;
        #pragma unroll
        for (int j = 0; j < 4; j++) {
            int col = n_base + j * 8 + 2 * q;
            float sa0 = ssa[col], sa1 = ssa[col + 1];
            float sd0 = ssd[col], sd1 = ssd[col + 1];
            psl += c[i][j][0] * sa0 + c[i][j][1] * sa1;
            pdl += c[i][j][0] * sd0 + c[i][j][1] * sd1;
            psh += c[i][j][2] * sa0 + c[i][j][3] * sa1;
            pdh += c[i][j][2] * sd0 + c[i][j][3] * sd1;
            __half2 lo = __floats2half2_rn(c[i][j][0], c[i][j][1]);
            __half2 hi = __floats2half2_rn(c[i][j][2], c[i][j][3]);
            stage[mr * SST + ((n_base + j * 8) >> 1) + q]       = *(unsigned*)&lo;
            stage[(mr + 8) * SST + ((n_base + j * 8) >> 1) + q] = *(unsigned*)&hi;
        }
        #pragma unroll
        for (int o = 1; o < 4; o <<= 1) {
            psl += __shfl_xor_sync(0xffffffffu, psl, o);
            pdl += __shfl_xor_sync(0xffffffffu, pdl, o);
            psh += __shfl_xor_sync(0xffffffffu, psh, o);
            pdh += __shfl_xor_sync(0xffffffffu, pdh, o);
        }
        if (q == 0) {
            int gl = row0 + mr, gh = gl + 8;
            if (gl < N_NODES) {
                ((float*)&g_as1[gl])[wn] = psl;
                ((float*)&g_ad1[gl])[wn] = pdl;
            }
            if (gh < N_NODES) {
                ((float*)&g_as1[gh])[wn] = psh;
                ((float*)&g_ad1[gh])[wn] = pdh;
            }
        }
    }
    __syncthreads();

    unsigned* gx = (unsigned*)g_xp1h;
    for (int idx = tid; idx < 128 * 64; idx += 256) {
        int r = idx >> 6, cc = idx & 63;
        int gr = row0 + r;
        if (gr < N_NODES) gx[gr * 64 + cc] = stage[r * SST + cc];
    }
}

// ---------------- CSR build (4 edges/thread) -----------------------------------
__global__ void count_k(const void* __restrict__ eiv) {
    int i4 = (blockIdx.x * blockDim.x + threadIdx.x) * 4;
    if (i4 >= E_TOT) return;
    int d0, d1, d2, d3;
    if (i4 < N_EDGES) {   // N_EDGES % 4 == 0: whole quad is real edges
        if (g_is64) {
            const longlong2* p = (const longlong2*)eiv + (N_EDGES + i4) / 2;
            longlong2 q0 = p[0], q1 = p[1];
            d0 = (int)q0.x; d1 = (int)q0.y; d2 = (int)q1.x; d3 = (int)q1.y;
        } else {
            int4 v = *((const int4*)((const int*)eiv + N_EDGES + i4));
            d0 = v.x; d1 = v.y; d2 = v.z; d3 = v.w;
        }
    } else {
        int b = i4 - N_EDGES;
        d0 = b; d1 = b + 1; d2 = b + 2; d3 = b + 3;
    }
    atomicAdd(&g_cnt[d0], 1);
    atomicAdd(&g_cnt[d1], 1);
    atomicAdd(&g_cnt[d2], 1);
    atomicAdd(&g_cnt[d3], 1);
}

__global__ __launch_bounds__(256) void scanA_k() {
    __shared__ int smem8[8];
    int i = blockIdx.x * 256 + threadIdx.x;
    int v = (i < N_NODES) ? g_cnt[i] : 0;
    int incl = block_scan_incl_256(v, smem8);
    if (i < N_NODES) g_excl[i] = incl - v;
    if (threadIdx.x == 255) g_bsum[blockIdx.x] = incl;
}
__global__ __launch_bounds__(256) void scanB_k() {
    __shared__ int smem8[8];
    int t = threadIdx.x;
    int v = (t < NB_SCAN) ? g_bsum[t] : 0;
    int incl = block_scan_incl_256(v, smem8);
    if (t < NB_SCAN) g_bsum[t] = incl - v;
    if (t == NB_SCAN - 1) g_rowstart[N_NODES] = incl;
}
__global__ __launch_bounds__(256) void scanC_k() {
    int i = blockIdx.x * 256 + threadIdx.x;
    if (i < N_NODES) {
        int r = g_excl[i] + g_bsum[blockIdx.x];
        g_rowstart[i] = r;
        g_cursor[i]   = r;
    }
}

// pure permutation scatter (4 edges/thread)
__global__ void scatter_k(const void* __restrict__ eiv) {
    int i4 = (blockIdx.x * blockDim.x + threadIdx.x) * 4;
    if (i4 >= E_TOT) return;
    int s0, s1, s2, s3, d0, d1, d2, d3;
    if (i4 < N_EDGES) {
        if (g_is64) {
            const longlong2* ps = (const longlong2*)eiv + i4 / 2;
            const longlong2* pd = (const longlong2*)eiv + (N_EDGES + i4) / 2;
            longlong2 a0 = ps[0], a1 = ps[1], b0 = pd[0], b1 = pd[1];
            s0 = (int)a0.x; s1 = (int)a0.y; s2 = (int)a1.x; s3 = (int)a1.y;
            d0 = (int)b0.x; d1 = (int)b0.y; d2 = (int)b1.x; d3 = (int)b1.y;
        } else {
            int4 sv = *((const int4*)((const int*)eiv + i4));
            int4 dv = *((const int4*)((const int*)eiv + N_EDGES + i4));
            s0 = sv.x; s1 = sv.y; s2 = sv.z; s3 = sv.w;
            d0 = dv.x; d1 = dv.y; d2 = dv.z; d3 = dv.w;
        }
    } else {
        int b = i4 - N_EDGES;
        s0 = d0 = b; s1 = d1 = b + 1; s2 = d2 = b + 2; s3 = d3 = b + 3;
    }
    g_srcs[atomicAdd(&g_cursor[d0], 1)] = s0;
    g_srcs[atomicAdd(&g_cursor[d1], 1)] = s1;
    g_srcs[atomicAdd(&g_cursor[d2], 1)] = s2;
    g_srcs[atomicAdd(&g_cursor[d3], 1)] = s3;
}

// ---------------- layer-1 gather + softmax + elu + layer-2 projection ----------
// One warp per dst. Chunked: 32 edge weights staged in smem, then half-warp
// per edge with uint4 (8-channel) feature loads -> 2 edges in flight per warp.
__global__ __launch_bounds__(256) void gather1_k(
    const float* __restrict__ b1, const float* __restrict__ W2,
    const float* __restrict__ aS2, const float* __restrict__ aD2)
{
    __shared__ float4 sw[8][32];
    __shared__ int    ssrc[8][32];
    int wslot = threadIdx.x >> 5;
    int gw = (blockIdx.x * blockDim.x + threadIdx.x) >> 5;
    int l = threadIdx.x & 31;
    if (gw >= N_NODES) return;
    int rs = g_rowstart[gw], re = g_rowstart[gw + 1];
    float4 ad = g_ad1[gw];

    int h  = l >> 4;        // half id: edge parity
    int hl = l & 15;        // channel-group: channels 8*hl .. 8*hl+7
    int head = hl >> 2;

    float z = 0.f;
    float c[8];
    #pragma unroll
    for (int i = 0; i < 8; i++) c[i] = 0.f;

    for (int jc = rs; jc < re; jc += 32) {
        int idx = jc + l;
        if (idx < re) {
            int s = g_srcs[idx];
            float4 a = g_as1[s];
            sw[wslot][l] = make_float4(__expf(leaky(a.x + ad.x)),
                                       __expf(leaky(a.y + ad.y)),
                                       __expf(leaky(a.z + ad.z)),
                                       __expf(leaky(a.w + ad.w)));
            ssrc[wslot][l] = s;
        }
        __syncwarp();
        int cnt = re - jc; if (cnt > 32) cnt = 32;
        #pragma unroll 4
        for (int e = h; e < cnt; e += 2) {
            int s = ssrc[wslot][e];
            float4 w4 = sw[wslot][e];
            float wv = (head == 0) ? w4.x : (head == 1) ? w4.y
                     : (head == 2) ? w4.z : w4.w;
            uint4 pk = *(const uint4*)&g_xp1h[s * HID + 8 * hl];
            float2 f0 = __half22float2(*(__half2*)&pk.x);
            float2 f1 = __half22float2(*(__half2*)&pk.y);
            float2 f2 = __half22float2(*(__half2*)&pk.z);
            float2 f3 = __half22float2(*(__half2*)&pk.w);
            z += wv;
            c[0] += wv * f0.x; c[1] += wv * f0.y;
            c[2] += wv * f1.x; c[3] += wv * f1.y;
            c[4] += wv * f2.x; c[5] += wv * f2.y;
            c[6] += wv * f3.x; c[7] += wv * f3.y;
        }
        __syncwarp();
    }

    // combine the two halves (lane l and l+16 hold same channels)
    z += __shfl_xor_sync(0xffffffffu, z, 16);
    #pragma unroll
    for (int i = 0; i < 8; i++) c[i] += __shfl_xor_sync(0xffffffffu, c[i], 16);

    float inv = 1.0f / (z + 1e-16f);
    float4 bA = *(const float4*)&b1[8 * hl];
    float4 bB = *(const float4*)&b1[8 * hl + 4];
    float hh[8];
    hh[0] = c[0] * inv + bA.x; hh[1] = c[1] * inv + bA.y;
    hh[2] = c[2] * inv + bA.z; hh[3] = c[3] * inv + bA.w;
    hh[4] = c[4] * inv + bB.x; hh[5] = c[5] * inv + bB.y;
    hh[6] = c[6] * inv + bB.z; hh[7] = c[7] * inv + bB.w;
    #pragma unroll
    for (int i = 0; i < 8; i++) hh[i] = hh[i] > 0.f ? hh[i] : expm1f(hh[i]);

    // layer-2 projection: rows 8*hl .. 8*hl+7 of W2 [128,2]
    float p0 = 0.f, p1 = 0.f;
    #pragma unroll
    for (int i = 0; i < 8; i += 2) {
        float4 w = *(const float4*)&W2[(8 * hl + i) * 2];
        p0 += hh[i] * w.x + hh[i + 1] * w.z;
        p1 += hh[i] * w.y + hh[i + 1] * w.w;
    }
    #pragma unroll
    for (int o = 8; o > 0; o >>= 1) {
        p0 += __shfl_xor_sync(0xffffffffu, p0, o);
        p1 += __shfl_xor_sync(0xffffffffu, p1, o);
    }
    if (l == 0) {
        float as2 = p0 * aS2[0] + p1 * aS2[1];
        float ad2 = p0 * aD2[0] + p1 * aD2[1];
        g_n2[gw] = make_float4(p0, p1, as2, ad2);
    }
}

// ---------------- layer-2 gather + output -------------------------------------
__global__ __launch_bounds__(256) void gather2_k(
    const float* __restrict__ b2, float* __restrict__ out)
{
    int gw = (blockIdx.x * blockDim.x + threadIdx.x) >> 5;
    int l = threadIdx.x & 31;
    if (gw >= N_NODES) return;
    int rs = g_rowstart[gw], re = g_rowstart[gw + 1];
    float ad = g_n2[gw].w;

    float z = 0.f, a0 = 0.f, a1 = 0.f;
    for (int j = rs + l; j < re; j += 32) {
        int s = __ldg(&g_srcs[j]);
        float4 n = __ldg(&g_n2[s]);
        float w = __expf(leaky(n.z + ad));
        z += w; a0 += w * n.x; a1 += w * n.y;
    }
    #pragma unroll
    for (int o = 16; o > 0; o >>= 1) {
        z  += __shfl_xor_sync(0xffffffffu, z, o);
        a0 += __shfl_xor_sync(0xffffffffu, a0, o);
        a1 += __shfl_xor_sync(0xffffffffu, a1, o);
    }
    if (l == 0) {
        float inv = 1.0f / (z + 1e-16f);
        out[gw * 2]     = a0 * inv + b2[0];
        out[gw * 2 + 1] = a1 * inv + b2[1];
    }
}

// ---------------- launch --------------------------------------------------------
extern "C" void kernel_launch(void* const* d_in, const int* in_sizes, int n_in,
                              void* d_out, int out_size) {
    const float* x     = (const float*)d_in[0];
    const float* fi    = (const float*)d_in[1];
    const float* W1    = (const float*)d_in[2];
    const float* attS1 = (const float*)d_in[3];
    const float* attD1 = (const float*)d_in[4];
    const float* b1    = (const float*)d_in[5];
    const float* W2    = (const float*)d_in[6];
    const float* attS2 = (const float*)d_in[7];
    const float* attD2 = (const float*)d_in[8];
    const float* b2    = (const float*)d_in[9];
    const void*  ei    = (const void*)d_in[10];
    float* out = (float*)d_out;

    cudaFuncSetAttribute(gemm_mma_k, cudaFuncAttributeMaxDynamicSharedMemorySize, GEMM_SMEM);

    prep_w_k<<<(IN_DIM * HID + 255) / 256, 256>>>(W1, fi);
    init_k<<<(N_NODES + 255) / 256, 256>>>((const int*)ei);
    gemm_mma_k<<<(N_NODES + 127) / 128, 256, GEMM_SMEM>>>(x, attS1, attD1);
    count_k<<<(E_TOT / 4 + 255) / 256, 256>>>(ei);
    scanA_k<<<NB_SCAN, 256>>>();
    scanB_k<<<1, 256>>>();
    scanC_k<<<NB_SCAN, 256>>>();
    scatter_k<<<(E_TOT / 4 + 255) / 256, 256>>>(ei);
    gather1_k<<<(N_NODES * 32 + 255) / 256, 256>>>(b1, W2, attS2, attD2);
    gather2_k<<<(N_NODES * 32 + 255) / 256, 256>>>(b2, out);
}

// round 9
// speedup vs baseline: 2.2739x; 1.0449x over previous
#include <cuda_runtime.h>
#include <cuda_fp16.h>
#include <math.h>
#include <stdint.h>

#define N_NODES 50000
#define N_EDGES 1600000
#define E_TOT   (N_EDGES + N_NODES)
#define IN_DIM  256
#define HID     128
#define HEADS   4
#define OUT_DIM 2
#define NEG_SLOPE 0.2f
#define NB_SCAN ((N_NODES + 255) / 256)

#define SA 264                        // smem row stride in halves (528B)
#define GEMM_SMEM (2 * 128 * SA * 2)  // A + B tiles = 135168 B

// ---------------- device scratch ---------------------------------------------
__device__ __half  g_xp1h[N_NODES * HID];
__device__ float4  g_as1[N_NODES];
__device__ float4  g_ad1[N_NODES];
__device__ float4  g_n2[N_NODES];
__device__ __half  g_wth[128 * SA];
__device__ float   g_sigf[IN_DIM];
__device__ int     g_cnt[N_NODES];
__device__ int     g_excl[N_NODES];
__device__ int     g_bsum[NB_SCAN];
__device__ int     g_rowstart[N_NODES + 1];
__device__ int     g_rankv[N_EDGES];       // per-edge rank within its dst row
__device__ int     g_srcs[E_TOT];
__device__ int     g_is64;

__device__ __forceinline__ float leaky(float e) { return e > 0.f ? e : NEG_SLOPE * e; }

__device__ __forceinline__ int block_scan_incl_256(int v, int* smem8) {
    int lane = threadIdx.x & 31, wid = threadIdx.x >> 5;
    int x = v;
    #pragma unroll
    for (int o = 1; o < 32; o <<= 1) {
        int y = __shfl_up_sync(0xffffffffu, x, o);
        if (lane >= o) x += y;
    }
    if (lane == 31) smem8[wid] = x;
    __syncthreads();
    if (wid == 0 && lane < 8) {
        int w = smem8[lane];
        #pragma unroll
        for (int o = 1; o < 8; o <<= 1) {
            int y = __shfl_up_sync(0xffu, w, o);
            if (lane >= o) w += y;
        }
        smem8[lane] = w;
    }
    __syncthreads();
    if (wid > 0) x += smem8[wid - 1];
    return x;
}

// ---------------- prep: W1^T -> fp16, sigmoid(fi), zero cnt, dtype probe ------
// NOTE: grid must cover N_NODES threads (g_cnt zeroing), not just IN_DIM*HID.
__global__ void prep_k(const float* __restrict__ W1, const float* __restrict__ fi,
                       const int* __restrict__ ei32) {
    int i = blockIdx.x * 256 + threadIdx.x;
    if (i < IN_DIM * HID) {
        int k = i >> 7, n = i & 127;
        g_wth[n * SA + k] = __float2half_rn(W1[i]);
    }
    if (i < IN_DIM) g_sigf[i] = 1.0f / (1.0f + __expf(-fi[i]));
    if (i < N_NODES) g_cnt[i] = 0;
    if (i == 0) {
        int all0 = 1;
        for (int k = 0; k < 64; k++)
            if (ei32[2 * k + 1] != 0) all0 = 0;
        g_is64 = all0;   // int64 node ids < 50000 -> odd words all zero
    }
}

// ---------------- layer-1 GEMM: warp-level mma.sync ----------------------------
__global__ __launch_bounds__(256, 1) void gemm_mma_k(
    const float* __restrict__ x,
    const float* __restrict__ attS, const float* __restrict__ attD)
{
    extern __shared__ __half sm[];
    __half* As = sm;                 // [128][SA]
    __half* Bs = sm + 128 * SA;      // [128][SA]
    __shared__ float sigf[IN_DIM];
    __shared__ float ssa[HID], ssd[HID];

    int tid = threadIdx.x;
    sigf[tid] = g_sigf[tid];
    if (tid < HID) { ssa[tid] = attS[tid]; ssd[tid] = attD[tid]; }

    {
        const uint4* wsrc = (const uint4*)g_wth;
        uint4* bd = (uint4*)Bs;
        #pragma unroll 4
        for (int i = tid; i < 128 * SA / 8; i += 256) bd[i] = wsrc[i];
    }
    __syncthreads();

    int row0 = blockIdx.x * 128;
    for (int f4 = tid; f4 < 8192; f4 += 256) {
        int r = f4 >> 6, c4 = (f4 & 63) * 4;
        int gr = row0 + r;
        float4 v = make_float4(0.f, 0.f, 0.f, 0.f);
        if (gr < N_NODES) v = *(const float4*)&x[(size_t)gr * IN_DIM + c4];
        float4 s = *(float4*)&sigf[c4];
        __half2 h0 = __floats2half2_rn(v.x * s.x, v.y * s.y);
        __half2 h1 = __floats2half2_rn(v.z * s.z, v.w * s.w);
        uint2 u;
        u.x = *(unsigned*)&h0;
        u.y = *(unsigned*)&h1;
        *(uint2*)&As[r * SA + c4] = u;
    }
    __syncthreads();

    int lane = tid & 31, wid = tid >> 5;
    int wm = wid >> 2, wn = wid & 3;
    int r4 = lane >> 2, q = lane & 3;
    int m_base = wm * 64;
    int n_base = wn * 32;

    float c[4][4][4];
    #pragma unroll
    for (int i = 0; i < 4; i++)
        #pragma unroll
        for (int j = 0; j < 4; j++)
            #pragma unroll
            for (int e = 0; e < 4; e++) c[i][j][e] = 0.f;

    const __half* a_base = As + (m_base + r4) * SA + 2 * q;
    const __half* b_base = Bs + (n_base + r4) * SA + 2 * q;

    #pragma unroll 1
    for (int ks = 0; ks < 16; ks++) {
        int k0 = ks * 16;
        unsigned bf[4][2];
        #pragma unroll
        for (int j = 0; j < 4; j++) {
            bf[j][0] = *(const unsigned*)&b_base[j * 8 * SA + k0];
            bf[j][1] = *(const unsigned*)&b_base[j * 8 * SA + k0 + 8];
        }
        #pragma unroll
        for (int i = 0; i < 4; i++) {
            const __half* ap = a_base + i * 16 * SA + k0;
            unsigned a0 = *(const unsigned*)ap;
            unsigned a1 = *(const unsigned*)(ap + 8 * SA);
            unsigned a2 = *(const unsigned*)(ap + 8);
            unsigned a3 = *(const unsigned*)(ap + 8 * SA + 8);
            #pragma unroll
            for (int j = 0; j < 4; j++) {
                asm volatile(
                    "mma.sync.aligned.m16n8k16.row.col.f32.f16.f16.f32 "
                    "{%0,%1,%2,%3}, {%4,%5,%6,%7}, {%8,%9}, {%0,%1,%2,%3};"
                    : "+f"(c[i][j][0]), "+f"(c[i][j][1]),
                      "+f"(c[i][j][2]), "+f"(c[i][j][3])
                    : "r"(a0), "r"(a1), "r"(a2), "r"(a3),
                      "r"(bf[j][0]), "r"(bf[j][1]));
            }
        }
    }
    __syncthreads();

    unsigned* stage = (unsigned*)sm;
    const int SST = 68;

    #pragma unroll
    for (int i = 0; i < 4; i++) {
        int mr = m_base + i * 16 + r4;
        float psl = 0.f, pdl = 0.f, psh = 0.f, pdh = 0.f;
        #pragma unroll
        for (int j = 0; j < 4; j++) {
            int col = n_base + j * 8 + 2 * q;
            float sa0 = ssa[col], sa1 = ssa[col + 1];
            float sd0 = ssd[col], sd1 = ssd[col + 1];
            psl += c[i][j][0] * sa0 + c[i][j][1] * sa1;
            pdl += c[i][j][0] * sd0 + c[i][j][1] * sd1;
            psh += c[i][j][2] * sa0 + c[i][j][3] * sa1;
            pdh += c[i][j][2] * sd0 + c[i][j][3] * sd1;
            __half2 lo = __floats2half2_rn(c[i][j][0], c[i][j][1]);
            __half2 hi = __floats2half2_rn(c[i][j][2], c[i][j][3]);
            stage[mr * SST + ((n_base + j * 8) >> 1) + q]       = *(unsigned*)&lo;
            stage[(mr + 8) * SST + ((n_base + j * 8) >> 1) + q] = *(unsigned*)&hi;
        }
        #pragma unroll
        for (int o = 1; o < 4; o <<= 1) {
            psl += __shfl_xor_sync(0xffffffffu, psl, o);
            pdl += __shfl_xor_sync(0xffffffffu, pdl, o);
            psh += __shfl_xor_sync(0xffffffffu, psh, o);
            pdh += __shfl_xor_sync(0xffffffffu, pdh, o);
        }
        if (q == 0) {
            int gl = row0 + mr, gh = gl + 8;
            if (gl < N_NODES) {
                ((float*)&g_as1[gl])[wn] = psl;
                ((float*)&g_ad1[gl])[wn] = pdl;
            }
            if (gh < N_NODES) {
                ((float*)&g_as1[gh])[wn] = psh;
                ((float*)&g_ad1[gh])[wn] = pdh;
            }
        }
    }
    __syncthreads();

    unsigned* gx = (unsigned*)g_xp1h;
    for (int idx = tid; idx < 128 * 64; idx += 256) {
        int r = idx >> 6, cc = idx & 63;
        int gr = row0 + r;
        if (gr < N_NODES) gx[gr * 64 + cc] = stage[r * SST + cc];
    }
}

// ---------------- CSR build: single atomic pass + rank placement ---------------
__global__ void rank_k(const void* __restrict__ eiv) {
    int i4 = (blockIdx.x * blockDim.x + threadIdx.x) * 4;
    if (i4 >= N_EDGES) return;
    int d0, d1, d2, d3;
    if (g_is64) {
        const longlong2* p = (const longlong2*)eiv + (N_EDGES + i4) / 2;
        longlong2 q0 = p[0], q1 = p[1];
        d0 = (int)q0.x; d1 = (int)q0.y; d2 = (int)q1.x; d3 = (int)q1.y;
    } else {
        int4 v = *((const int4*)((const int*)eiv + N_EDGES + i4));
        d0 = v.x; d1 = v.y; d2 = v.z; d3 = v.w;
    }
    int4 r;
    r.x = atomicAdd(&g_cnt[d0], 1);
    r.y = atomicAdd(&g_cnt[d1], 1);
    r.z = atomicAdd(&g_cnt[d2], 1);
    r.w = atomicAdd(&g_cnt[d3], 1);
    *(int4*)&g_rankv[i4] = r;
}

__global__ __launch_bounds__(256) void scanA_k() {
    __shared__ int smem8[8];
    int i = blockIdx.x * 256 + threadIdx.x;
    // +1: self-loop appended at the END of each row
    int v = (i < N_NODES) ? g_cnt[i] + 1 : 0;
    int incl = block_scan_incl_256(v, smem8);
    if (i < N_NODES) g_excl[i] = incl - v;
    if (threadIdx.x == 255) g_bsum[blockIdx.x] = incl;
}
__global__ __launch_bounds__(256) void scanB_k() {
    __shared__ int smem8[8];
    int t = threadIdx.x;
    int v = (t < NB_SCAN) ? g_bsum[t] : 0;
    int incl = block_scan_incl_256(v, smem8);
    if (t < NB_SCAN) g_bsum[t] = incl - v;
    if (t == NB_SCAN - 1) g_rowstart[N_NODES] = incl;
}
// rowstart + self-loop placement (self-loop = last slot of each row)
__global__ __launch_bounds__(256) void scanC_k() {
    int i = blockIdx.x * 256 + threadIdx.x;
    if (i < N_NODES) {
        int r = g_excl[i] + g_bsum[blockIdx.x];
        g_rowstart[i] = r;
        g_srcs[r + g_cnt[i]] = i;     // self-loop slot
    }
}

// placement: no atomics, position = rowstart[dst] + rank
__global__ void place_k(const void* __restrict__ eiv) {
    int i4 = (blockIdx.x * blockDim.x + threadIdx.x) * 4;
    if (i4 >= N_EDGES) return;
    int s0, s1, s2, s3, d0, d1, d2, d3;
    if (g_is64) {
        const longlong2* ps = (const longlong2*)eiv + i4 / 2;
        const longlong2* pd = (const longlong2*)eiv + (N_EDGES + i4) / 2;
        longlong2 a0 = ps[0], a1 = ps[1], b0 = pd[0], b1 = pd[1];
        s0 = (int)a0.x; s1 = (int)a0.y; s2 = (int)a1.x; s3 = (int)a1.y;
        d0 = (int)b0.x; d1 = (int)b0.y; d2 = (int)b1.x; d3 = (int)b1.y;
    } else {
        int4 sv = *((const int4*)((const int*)eiv + i4));
        int4 dv = *((const int4*)((const int*)eiv + N_EDGES + i4));
        s0 = sv.x; s1 = sv.y; s2 = sv.z; s3 = sv.w;
        d0 = dv.x; d1 = dv.y; d2 = dv.z; d3 = dv.w;
    }
    int4 r = *(const int4*)&g_rankv[i4];
    g_srcs[g_rowstart[d0] + r.x] = s0;
    g_srcs[g_rowstart[d1] + r.y] = s1;
    g_srcs[g_rowstart[d2] + r.z] = s2;
    g_srcs[g_rowstart[d3] + r.w] = s3;
}

// ---------------- layer-1 gather + softmax + elu + layer-2 projection ----------
__global__ __launch_bounds__(256) void gather1_k(
    const float* __restrict__ b1, const float* __restrict__ W2,
    const float* __restrict__ aS2, const float* __restrict__ aD2)
{
    __shared__ float4 sw[8][32];
    __shared__ int    ssrc[8][32];
    int wslot = threadIdx.x >> 5;
    int gw = (blockIdx.x * blockDim.x + threadIdx.x) >> 5;
    int l = threadIdx.x & 31;
    if (gw >= N_NODES) return;
    int rs = g_rowstart[gw], re = g_rowstart[gw + 1];
    float4 ad = g_ad1[gw];

    int h  = l >> 4;
    int hl = l & 15;
    int head = hl >> 2;

    float z = 0.f;
    float c[8];
    #pragma unroll
    for (int i = 0; i < 8; i++) c[i] = 0.f;

    for (int jc = rs; jc < re; jc += 32) {
        int idx = jc + l;
        if (idx < re) {
            int s = g_srcs[idx];
            float4 a = g_as1[s];
            sw[wslot][l] = make_float4(__expf(leaky(a.x + ad.x)),
                                       __expf(leaky(a.y + ad.y)),
                                       __expf(leaky(a.z + ad.z)),
                                       __expf(leaky(a.w + ad.w)));
            ssrc[wslot][l] = s;
        }
        __syncwarp();
        int cnt = re - jc; if (cnt > 32) cnt = 32;
        #pragma unroll 4
        for (int e = h; e < cnt; e += 2) {
            int s = ssrc[wslot][e];
            float4 w4 = sw[wslot][e];
            float wv = (head == 0) ? w4.x : (head == 1) ? w4.y
                     : (head == 2) ? w4.z : w4.w;
            uint4 pk = *(const uint4*)&g_xp1h[s * HID + 8 * hl];
            float2 f0 = __half22float2(*(__half2*)&pk.x);
            float2 f1 = __half22float2(*(__half2*)&pk.y);
            float2 f2 = __half22float2(*(__half2*)&pk.z);
            float2 f3 = __half22float2(*(__half2*)&pk.w);
            z += wv;
            c[0] += wv * f0.x; c[1] += wv * f0.y;
            c[2] += wv * f1.x; c[3] += wv * f1.y;
            c[4] += wv * f2.x; c[5] += wv * f2.y;
            c[6] += wv * f3.x; c[7] += wv * f3.y;
        }
        __syncwarp();
    }

    z += __shfl_xor_sync(0xffffffffu, z, 16);
    #pragma unroll
    for (int i = 0; i < 8; i++) c[i] += __shfl_xor_sync(0xffffffffu, c[i], 16);

    float inv = 1.0f / (z + 1e-16f);
    float4 bA = *(const float4*)&b1[8 * hl];
    float4 bB = *(const float4*)&b1[8 * hl + 4];
    float hh[8];
    hh[0] = c[0] * inv + bA.x; hh[1] = c[1] * inv + bA.y;
    hh[2] = c[2] * inv + bA.z; hh[3] = c[3] * inv + bA.w;
    hh[4] = c[4] * inv + bB.x; hh[5] = c[5] * inv + bB.y;
    hh[6] = c[6] * inv + bB.z; hh[7] = c[7] * inv + bB.w;
    #pragma unroll
    for (int i = 0; i < 8; i++) hh[i] = hh[i] > 0.f ? hh[i] : expm1f(hh[i]);

    float p0 = 0.f, p1 = 0.f;
    #pragma unroll
    for (int i = 0; i < 8; i += 2) {
        float4 w = *(const float4*)&W2[(8 * hl + i) * 2];
        p0 += hh[i] * w.x + hh[i + 1] * w.z;
        p1 += hh[i] * w.y + hh[i + 1] * w.w;
    }
    #pragma unroll
    for (int o = 8; o > 0; o >>= 1) {
        p0 += __shfl_xor_sync(0xffffffffu, p0, o);
        p1 += __shfl_xor_sync(0xffffffffu, p1, o);
    }
    if (l == 0) {
        float as2 = p0 * aS2[0] + p1 * aS2[1];
        float ad2 = p0 * aD2[0] + p1 * aD2[1];
        g_n2[gw] = make_float4(p0, p1, as2, ad2);
    }
}

// ---------------- layer-2 gather + output -------------------------------------
__global__ __launch_bounds__(256) void gather2_k(
    const float* __restrict__ b2, float* __restrict__ out)
{
    int gw = (blockIdx.x * blockDim.x + threadIdx.x) >> 5;
    int l = threadIdx.x & 31;
    if (gw >= N_NODES) return;
    int rs = g_rowstart[gw], re = g_rowstart[gw + 1];
    float ad = g_n2[gw].w;

    float z = 0.f, a0 = 0.f, a1 = 0.f;
    for (int j = rs + l; j < re; j += 32) {
        int s = __ldg(&g_srcs[j]);
        float4 n = __ldg(&g_n2[s]);
        float w = __expf(leaky(n.z + ad));
        z += w; a0 += w * n.x; a1 += w * n.y;
    }
    #pragma unroll
    for (int o = 16; o > 0; o >>= 1) {
        z  += __shfl_xor_sync(0xffffffffu, z, o);
        a0 += __shfl_xor_sync(0xffffffffu, a0, o);
        a1 += __shfl_xor_sync(0xffffffffu, a1, o);
    }
    if (l == 0) {
        float inv = 1.0f / (z + 1e-16f);
        out[gw * 2]     = a0 * inv + b2[0];
        out[gw * 2 + 1] = a1 * inv + b2[1];
    }
}

// ---------------- launch --------------------------------------------------------
extern "C" void kernel_launch(void* const* d_in, const int* in_sizes, int n_in,
                              void* d_out, int out_size) {
    const float* x     = (const float*)d_in[0];
    const float* fi    = (const float*)d_in[1];
    const float* W1    = (const float*)d_in[2];
    const float* attS1 = (const float*)d_in[3];
    const float* attD1 = (const float*)d_in[4];
    const float* b1    = (const float*)d_in[5];
    const float* W2    = (const float*)d_in[6];
    const float* attS2 = (const float*)d_in[7];
    const float* attD2 = (const float*)d_in[8];
    const float* b2    = (const float*)d_in[9];
    const void*  ei    = (const void*)d_in[10];
    float* out = (float*)d_out;

    cudaFuncSetAttribute(gemm_mma_k, cudaFuncAttributeMaxDynamicSharedMemorySize, GEMM_SMEM);

    // grid covers N_NODES (cnt zeroing) AND IN_DIM*HID (weight transpose)
    int prep_threads = (N_NODES > IN_DIM * HID) ? N_NODES : IN_DIM * HID;
    prep_k<<<(prep_threads + 255) / 256, 256>>>(W1, fi, (const int*)ei);
    gemm_mma_k<<<(N_NODES + 127) / 128, 256, GEMM_SMEM>>>(x, attS1, attD1);
    rank_k<<<(N_EDGES / 4 + 255) / 256, 256>>>(ei);
    scanA_k<<<NB_SCAN, 256>>>();
    scanB_k<<<1, 256>>>();
    scanC_k<<<NB_SCAN, 256>>>();
    place_k<<<(N_EDGES / 4 + 255) / 256, 256>>>(ei);
    gather1_k<<<(N_NODES * 32 + 255) / 256, 256>>>(b1, W2, attS2, attD2);
    gather2_k<<<(N_NODES * 32 + 255) / 256, 256>>>(b2, out);
}

// round 10
// speedup vs baseline: 2.3847x; 1.0487x over previous
#include <cuda_runtime.h>
#include <cuda_fp16.h>
#include <math.h>
#include <stdint.h>

#define N_NODES 50000
#define N_EDGES 1600000
#define E_TOT   (N_EDGES + N_NODES)
#define IN_DIM  256
#define HID     128
#define HEADS   4
#define OUT_DIM 2
#define NEG_SLOPE 0.2f
#define NB_SCAN ((N_NODES + 255) / 256)

#define SA 264                        // smem row stride in halves (528B)
#define GEMM_SMEM (2 * 128 * SA * 2)  // A + B tiles = 135168 B

// ---------------- device scratch ---------------------------------------------
__device__ __half  g_xp1h[N_NODES * HID];
__device__ float4  g_as1[N_NODES];
__device__ float4  g_ad1[N_NODES];
__device__ float4  g_n2[N_NODES];
__device__ __half  g_wth[128 * SA];
__device__ float   g_sigf[IN_DIM];
__device__ int     g_cnt[N_NODES];
__device__ int     g_excl[N_NODES];
__device__ int     g_bsum[NB_SCAN];
__device__ int     g_rowstart[N_NODES + 1];
__device__ int     g_rankv[N_EDGES];       // per-edge rank within its dst row
__device__ int     g_srcs[E_TOT];
__device__ int     g_is64;

__device__ __forceinline__ float leaky(float e) { return e > 0.f ? e : NEG_SLOPE * e; }

__device__ __forceinline__ int block_scan_incl_256(int v, int* smem8) {
    int lane = threadIdx.x & 31, wid = threadIdx.x >> 5;
    int x = v;
    #pragma unroll
    for (int o = 1; o < 32; o <<= 1) {
        int y = __shfl_up_sync(0xffffffffu, x, o);
        if (lane >= o) x += y;
    }
    if (lane == 31) smem8[wid] = x;
    __syncthreads();
    if (wid == 0 && lane < 8) {
        int w = smem8[lane];
        #pragma unroll
        for (int o = 1; o < 8; o <<= 1) {
            int y = __shfl_up_sync(0xffu, w, o);
            if (lane >= o) w += y;
        }
        smem8[lane] = w;
    }
    __syncthreads();
    if (wid > 0) x += smem8[wid - 1];
    return x;
}

// ---------------- prep: W1^T -> fp16, sigmoid(fi), zero cnt, dtype probe ------
__global__ void prep_k(const float* __restrict__ W1, const float* __restrict__ fi,
                       const int* __restrict__ ei32) {
    int i = blockIdx.x * 256 + threadIdx.x;
    if (i < IN_DIM * HID) {
        int k = i >> 7, n = i & 127;
        g_wth[n * SA + k] = __float2half_rn(W1[i]);
    }
    if (i < IN_DIM) g_sigf[i] = 1.0f / (1.0f + __expf(-fi[i]));
    if (i < N_NODES) g_cnt[i] = 0;
    if (i == 0) {
        int all0 = 1;
        for (int k = 0; k < 64; k++)
            if (ei32[2 * k + 1] != 0) all0 = 0;
        g_is64 = all0;   // int64 node ids < 50000 -> odd words all zero
    }
}

// ---------------- layer-1 GEMM: warp-level mma.sync ----------------------------
__global__ __launch_bounds__(256, 1) void gemm_mma_k(
    const float* __restrict__ x,
    const float* __restrict__ attS, const float* __restrict__ attD)
{
    extern __shared__ __half sm[];
    __half* As = sm;                 // [128][SA]
    __half* Bs = sm + 128 * SA;      // [128][SA]
    __shared__ float sigf[IN_DIM];
    __shared__ float ssa[HID], ssd[HID];

    int tid = threadIdx.x;
    sigf[tid] = g_sigf[tid];
    if (tid < HID) { ssa[tid] = attS[tid]; ssd[tid] = attD[tid]; }

    {
        const uint4* wsrc = (const uint4*)g_wth;
        uint4* bd = (uint4*)Bs;
        #pragma unroll 4
        for (int i = tid; i < 128 * SA / 8; i += 256) bd[i] = wsrc[i];
    }
    __syncthreads();

    int row0 = blockIdx.x * 128;
    for (int f4 = tid; f4 < 8192; f4 += 256) {
        int r = f4 >> 6, c4 = (f4 & 63) * 4;
        int gr = row0 + r;
        float4 v = make_float4(0.f, 0.f, 0.f, 0.f);
        if (gr < N_NODES) v = *(const float4*)&x[(size_t)gr * IN_DIM + c4];
        float4 s = *(float4*)&sigf[c4];
        __half2 h0 = __floats2half2_rn(v.x * s.x, v.y * s.y);
        __half2 h1 = __floats2half2_rn(v.z * s.z, v.w * s.w);
        uint2 u;
        u.x = *(unsigned*)&h0;
        u.y = *(unsigned*)&h1;
        *(uint2*)&As[r * SA + c4] = u;
    }
    __syncthreads();

    int lane = tid & 31, wid = tid >> 5;
    int wm = wid >> 2, wn = wid & 3;
    int r4 = lane >> 2, q = lane & 3;
    int m_base = wm * 64;
    int n_base = wn * 32;

    float c[4][4][4];
    #pragma unroll
    for (int i = 0; i < 4; i++)
        #pragma unroll
        for (int j = 0; j < 4; j++)
            #pragma unroll
            for (int e = 0; e < 4; e++) c[i][j][e] = 0.f;

    const __half* a_base = As + (m_base + r4) * SA + 2 * q;
    const __half* b_base = Bs + (n_base + r4) * SA + 2 * q;

    #pragma unroll 1
    for (int ks = 0; ks < 16; ks++) {
        int k0 = ks * 16;
        unsigned bf[4][2];
        #pragma unroll
        for (int j = 0; j < 4; j++) {
            bf[j][0] = *(const unsigned*)&b_base[j * 8 * SA + k0];
            bf[j][1] = *(const unsigned*)&b_base[j * 8 * SA + k0 + 8];
        }
        #pragma unroll
        for (int i = 0; i < 4; i++) {
            const __half* ap = a_base + i * 16 * SA + k0;
            unsigned a0 = *(const unsigned*)ap;
            unsigned a1 = *(const unsigned*)(ap + 8 * SA);
            unsigned a2 = *(const unsigned*)(ap + 8);
            unsigned a3 = *(const unsigned*)(ap + 8 * SA + 8);
            #pragma unroll
            for (int j = 0; j < 4; j++) {
                asm volatile(
                    "mma.sync.aligned.m16n8k16.row.col.f32.f16.f16.f32 "
                    "{%0,%1,%2,%3}, {%4,%5,%6,%7}, {%8,%9}, {%0,%1,%2,%3};"
                    : "+f"(c[i][j][0]), "+f"(c[i][j][1]),
                      "+f"(c[i][j][2]), "+f"(c[i][j][3])
                    : "r"(a0), "r"(a1), "r"(a2), "r"(a3),
                      "r"(bf[j][0]), "r"(bf[j][1]));
            }
        }
    }
    __syncthreads();

    unsigned* stage = (unsigned*)sm;
    const int SST = 68;

    #pragma unroll
    for (int i = 0; i < 4; i++) {
        int mr = m_base + i * 16 + r4;
        float psl = 0.f, pdl = 0.f, psh = 0.f, pdh = 0.f;
        #pragma unroll
        for (int j = 0; j < 4; j++) {
            int col = n_base + j * 8 + 2 * q;
            float sa0 = ssa[col], sa1 = ssa[col + 1];
            float sd0 = ssd[col], sd1 = ssd[col + 1];
            psl += c[i][j][0] * sa0 + c[i][j][1] * sa1;
            pdl += c[i][j][0] * sd0 + c[i][j][1] * sd1;
            psh += c[i][j][2] * sa0 + c[i][j][3] * sa1;
            pdh += c[i][j][2] * sd0 + c[i][j][3] * sd1;
            __half2 lo = __floats2half2_rn(c[i][j][0], c[i][j][1]);
            __half2 hi = __floats2half2_rn(c[i][j][2], c[i][j][3]);
            stage[mr * SST + ((n_base + j * 8) >> 1) + q]       = *(unsigned*)&lo;
            stage[(mr + 8) * SST + ((n_base + j * 8) >> 1) + q] = *(unsigned*)&hi;
        }
        #pragma unroll
        for (int o = 1; o < 4; o <<= 1) {
            psl += __shfl_xor_sync(0xffffffffu, psl, o);
            pdl += __shfl_xor_sync(0xffffffffu, pdl, o);
            psh += __shfl_xor_sync(0xffffffffu, psh, o);
            pdh += __shfl_xor_sync(0xffffffffu, pdh, o);
        }
        if (q == 0) {
            int gl = row0 + mr, gh = gl + 8;
            if (gl < N_NODES) {
                ((float*)&g_as1[gl])[wn] = psl;
                ((float*)&g_ad1[gl])[wn] = pdl;
            }
            if (gh < N_NODES) {
                ((float*)&g_as1[gh])[wn] = psh;
                ((float*)&g_ad1[gh])[wn] = pdh;
            }
        }
    }
    __syncthreads();

    unsigned* gx = (unsigned*)g_xp1h;
    for (int idx = tid; idx < 128 * 64; idx += 256) {
        int r = idx >> 6, cc = idx & 63;
        int gr = row0 + r;
        if (gr < N_NODES) gx[gr * 64 + cc] = stage[r * SST + cc];
    }
}

// ---------------- CSR build: single atomic pass + rank placement ---------------
__global__ void rank_k(const void* __restrict__ eiv) {
    int i4 = (blockIdx.x * blockDim.x + threadIdx.x) * 4;
    if (i4 >= N_EDGES) return;
    int d0, d1, d2, d3;
    if (g_is64) {
        const longlong2* p = (const longlong2*)eiv + (N_EDGES + i4) / 2;
        longlong2 q0 = p[0], q1 = p[1];
        d0 = (int)q0.x; d1 = (int)q0.y; d2 = (int)q1.x; d3 = (int)q1.y;
    } else {
        int4 v = *((const int4*)((const int*)eiv + N_EDGES + i4));
        d0 = v.x; d1 = v.y; d2 = v.z; d3 = v.w;
    }
    int4 r;
    r.x = atomicAdd(&g_cnt[d0], 1);
    r.y = atomicAdd(&g_cnt[d1], 1);
    r.z = atomicAdd(&g_cnt[d2], 1);
    r.w = atomicAdd(&g_cnt[d3], 1);
    *(int4*)&g_rankv[i4] = r;
}

__global__ __launch_bounds__(256) void scanA_k() {
    __shared__ int smem8[8];
    int i = blockIdx.x * 256 + threadIdx.x;
    int v = (i < N_NODES) ? g_cnt[i] + 1 : 0;   // +1 self-loop at row end
    int incl = block_scan_incl_256(v, smem8);
    if (i < N_NODES) g_excl[i] = incl - v;
    if (threadIdx.x == 255) g_bsum[blockIdx.x] = incl;
}
__global__ __launch_bounds__(256) void scanB_k() {
    __shared__ int smem8[8];
    int t = threadIdx.x;
    int v = (t < NB_SCAN) ? g_bsum[t] : 0;
    int incl = block_scan_incl_256(v, smem8);
    if (t < NB_SCAN) g_bsum[t] = incl - v;
    if (t == NB_SCAN - 1) g_rowstart[N_NODES] = incl;
}
__global__ __launch_bounds__(256) void scanC_k() {
    int i = blockIdx.x * 256 + threadIdx.x;
    if (i < N_NODES) {
        int r = g_excl[i] + g_bsum[blockIdx.x];
        g_rowstart[i] = r;
        g_srcs[r + g_cnt[i]] = i;     // self-loop slot
    }
}

// placement: no atomics, position = rowstart[dst] + rank
__global__ void place_k(const void* __restrict__ eiv) {
    int i4 = (blockIdx.x * blockDim.x + threadIdx.x) * 4;
    if (i4 >= N_EDGES) return;
    int s0, s1, s2, s3, d0, d1, d2, d3;
    if (g_is64) {
        const longlong2* ps = (const longlong2*)eiv + i4 / 2;
        const longlong2* pd = (const longlong2*)eiv + (N_EDGES + i4) / 2;
        longlong2 a0 = ps[0], a1 = ps[1], b0 = pd[0], b1 = pd[1];
        s0 = (int)a0.x; s1 = (int)a0.y; s2 = (int)a1.x; s3 = (int)a1.y;
        d0 = (int)b0.x; d1 = (int)b0.y; d2 = (int)b1.x; d3 = (int)b1.y;
    } else {
        int4 sv = *((const int4*)((const int*)eiv + i4));
        int4 dv = *((const int4*)((const int*)eiv + N_EDGES + i4));
        s0 = sv.x; s1 = sv.y; s2 = sv.z; s3 = sv.w;
        d0 = dv.x; d1 = dv.y; d2 = dv.z; d3 = dv.w;
    }
    int4 r = *(const int4*)&g_rankv[i4];
    g_srcs[g_rowstart[d0] + r.x] = s0;
    g_srcs[g_rowstart[d1] + r.y] = s1;
    g_srcs[g_rowstart[d2] + r.z] = s2;
    g_srcs[g_rowstart[d3] + r.w] = s3;
}

// ---------------- layer-1 gather + softmax + elu + layer-2 projection ----------
__global__ __launch_bounds__(256) void gather1_k(
    const float* __restrict__ b1, const float* __restrict__ W2,
    const float* __restrict__ aS2, const float* __restrict__ aD2)
{
    __shared__ float4 sw[8][32];
    __shared__ int    ssrc[8][32];
    int wslot = threadIdx.x >> 5;
    int gw = (blockIdx.x * blockDim.x + threadIdx.x) >> 5;
    int l = threadIdx.x & 31;
    if (gw >= N_NODES) return;
    int rs = g_rowstart[gw], re = g_rowstart[gw + 1];
    float4 ad = g_ad1[gw];

    int h  = l >> 4;
    int hl = l & 15;
    int head = hl >> 2;

    float z = 0.f;
    float c[8];
    #pragma unroll
    for (int i = 0; i < 8; i++) c[i] = 0.f;

    for (int jc = rs; jc < re; jc += 32) {
        int idx = jc + l;
        if (idx < re) {
            int s = g_srcs[idx];
            float4 a = g_as1[s];
            sw[wslot][l] = make_float4(__expf(leaky(a.x + ad.x)),
                                       __expf(leaky(a.y + ad.y)),
                                       __expf(leaky(a.z + ad.z)),
                                       __expf(leaky(a.w + ad.w)));
            ssrc[wslot][l] = s;
        }
        __syncwarp();
        int cnt = re - jc; if (cnt > 32) cnt = 32;
        #pragma unroll 4
        for (int e = h; e < cnt; e += 2) {
            int s = ssrc[wslot][e];
            float4 w4 = sw[wslot][e];
            float wv = (head == 0) ? w4.x : (head == 1) ? w4.y
                     : (head == 2) ? w4.z : w4.w;
            uint4 pk = *(const uint4*)&g_xp1h[s * HID + 8 * hl];
            float2 f0 = __half22float2(*(__half2*)&pk.x);
            float2 f1 = __half22float2(*(__half2*)&pk.y);
            float2 f2 = __half22float2(*(__half2*)&pk.z);
            float2 f3 = __half22float2(*(__half2*)&pk.w);
            z += wv;
            c[0] += wv * f0.x; c[1] += wv * f0.y;
            c[2] += wv * f1.x; c[3] += wv * f1.y;
            c[4] += wv * f2.x; c[5] += wv * f2.y;
            c[6] += wv * f3.x; c[7] += wv * f3.y;
        }
        __syncwarp();
    }

    z += __shfl_xor_sync(0xffffffffu, z, 16);
    #pragma unroll
    for (int i = 0; i < 8; i++) c[i] += __shfl_xor_sync(0xffffffffu, c[i], 16);

    float inv = 1.0f / (z + 1e-16f);
    float4 bA = *(const float4*)&b1[8 * hl];
    float4 bB = *(const float4*)&b1[8 * hl + 4];
    float hh[8];
    hh[0] = c[0] * inv + bA.x; hh[1] = c[1] * inv + bA.y;
    hh[2] = c[2] * inv + bA.z; hh[3] = c[3] * inv + bA.w;
    hh[4] = c[4] * inv + bB.x; hh[5] = c[5] * inv + bB.y;
    hh[6] = c[6] * inv + bB.z; hh[7] = c[7] * inv + bB.w;
    #pragma unroll
    for (int i = 0; i < 8; i++) hh[i] = hh[i] > 0.f ? hh[i] : expm1f(hh[i]);

    float p0 = 0.f, p1 = 0.f;
    #pragma unroll
    for (int i = 0; i < 8; i += 2) {
        float4 w = *(const float4*)&W2[(8 * hl + i) * 2];
        p0 += hh[i] * w.x + hh[i + 1] * w.z;
        p1 += hh[i] * w.y + hh[i + 1] * w.w;
    }
    #pragma unroll
    for (int o = 8; o > 0; o >>= 1) {
        p0 += __shfl_xor_sync(0xffffffffu, p0, o);
        p1 += __shfl_xor_sync(0xffffffffu, p1, o);
    }
    if (l == 0) {
        float as2 = p0 * aS2[0] + p1 * aS2[1];
        float ad2 = p0 * aD2[0] + p1 * aD2[1];
        g_n2[gw] = make_float4(p0, p1, as2, ad2);
    }
}

// ---------------- layer-2 gather + output -------------------------------------
__global__ __launch_bounds__(256) void gather2_k(
    const float* __restrict__ b2, float* __restrict__ out)
{
    int gw = (blockIdx.x * blockDim.x + threadIdx.x) >> 5;
    int l = threadIdx.x & 31;
    if (gw >= N_NODES) return;
    int rs = g_rowstart[gw], re = g_rowstart[gw + 1];
    float ad = g_n2[gw].w;

    float z = 0.f, a0 = 0.f, a1 = 0.f;
    for (int j = rs + l; j < re; j += 32) {
        int s = __ldg(&g_srcs[j]);
        float4 n = __ldg(&g_n2[s]);
        float w = __expf(leaky(n.z + ad));
        z += w; a0 += w * n.x; a1 += w * n.y;
    }
    #pragma unroll
    for (int o = 16; o > 0; o >>= 1) {
        z  += __shfl_xor_sync(0xffffffffu, z, o);
        a0 += __shfl_xor_sync(0xffffffffu, a0, o);
        a1 += __shfl_xor_sync(0xffffffffu, a1, o);
    }
    if (l == 0) {
        float inv = 1.0f / (z + 1e-16f);
        out[gw * 2]     = a0 * inv + b2[0];
        out[gw * 2 + 1] = a1 * inv + b2[1];
    }
}

// ---------------- launch: fork CSR build onto a side stream --------------------
extern "C" void kernel_launch(void* const* d_in, const int* in_sizes, int n_in,
                              void* d_out, int out_size) {
    const float* x     = (const float*)d_in[0];
    const float* fi    = (const float*)d_in[1];
    const float* W1    = (const float*)d_in[2];
    const float* attS1 = (const float*)d_in[3];
    const float* attD1 = (const float*)d_in[4];
    const float* b1    = (const float*)d_in[5];
    const float* W2    = (const float*)d_in[6];
    const float* attS2 = (const float*)d_in[7];
    const float* attD2 = (const float*)d_in[8];
    const float* b2    = (const float*)d_in[9];
    const void*  ei    = (const void*)d_in[10];
    float* out = (float*)d_out;

    // one-time resources (no device memory involved; identical work every call)
    static cudaStream_t s2 = nullptr;
    static cudaEvent_t evFork = nullptr, evJoin = nullptr;
    if (s2 == nullptr) {
        cudaStreamCreateWithFlags(&s2, cudaStreamNonBlocking);
        cudaEventCreateWithFlags(&evFork, cudaEventDisableTiming);
        cudaEventCreateWithFlags(&evJoin, cudaEventDisableTiming);
        cudaFuncSetAttribute(gemm_mma_k, cudaFuncAttributeMaxDynamicSharedMemorySize, GEMM_SMEM);
    }

    int prep_threads = (N_NODES > IN_DIM * HID) ? N_NODES : IN_DIM * HID;
    prep_k<<<(prep_threads + 255) / 256, 256>>>(W1, fi, (const int*)ei);

    // fork: CSR build chain on s2, concurrent with the GEMM
    cudaEventRecord(evFork, 0);
    cudaStreamWaitEvent(s2, evFork, 0);
    rank_k<<<(N_EDGES / 4 + 255) / 256, 256, 0, s2>>>(ei);
    scanA_k<<<NB_SCAN, 256, 0, s2>>>();
    scanB_k<<<1, 256, 0, s2>>>();
    scanC_k<<<NB_SCAN, 256, 0, s2>>>();
    place_k<<<(N_EDGES / 4 + 255) / 256, 256, 0, s2>>>(ei);
    cudaEventRecord(evJoin, s2);

    gemm_mma_k<<<(N_NODES + 127) / 128, 256, GEMM_SMEM>>>(x, attS1, attD1);

    // join: gathers need both the GEMM outputs and the CSR
    cudaStreamWaitEvent(0, evJoin, 0);
    gather1_k<<<(N_NODES * 32 + 255) / 256, 256>>>(b1, W2, attS2, attD2);
    gather2_k<<<(N_NODES * 32 + 255) / 256, 256>>>(b2, out);
}